// round 8
// baseline (speedup 1.0000x reference)
#include <cuda_runtime.h>
#include <cuda_bf16.h>
#include <cstdint>

#define D_DIM 512
#define QMAX  2048
#define NPAD  100096   // 782 * 128

// ---------------- scratch (device globals; no allocation allowed) -----------
__device__ __align__(16) float g_d2[(size_t)QMAX * 100000];  // approx d2 (bf16 GEMM)
__device__ float g_x2[QMAX];
__device__ float g_t2[NPAD];
__device__ __align__(256) __nv_bfloat16 g_xb[(size_t)QMAX * D_DIM];
__device__ __align__(256) __nv_bfloat16 g_tb[(size_t)NPAD * D_DIM];

// ---------------- kernel: fused fp32->bf16 convert + row norms --------------
__global__ void convert_norm(const float* __restrict__ src, int rows_valid,
                             int rows_total, int which)
{
    int gw   = (blockIdx.x * blockDim.x + threadIdx.x) >> 5;
    int lane = threadIdx.x & 31;
    if (gw >= rows_total) return;
    __nv_bfloat162* dst =
        reinterpret_cast<__nv_bfloat162*>(which ? g_tb : g_xb) + (size_t)gw * (D_DIM / 2);
    if (gw < rows_valid) {
        const float4* r4 = reinterpret_cast<const float4*>(src + (size_t)gw * D_DIM);
        float s = 0.f;
#pragma unroll
        for (int j = 0; j < 4; ++j) {
            float4 v = r4[lane + j * 32];
            s += v.x * v.x + v.y * v.y + v.z * v.z + v.w * v.w;
            dst[(lane + j * 32) * 2 + 0] = __floats2bfloat162_rn(v.x, v.y);
            dst[(lane + j * 32) * 2 + 1] = __floats2bfloat162_rn(v.z, v.w);
        }
#pragma unroll
        for (int o = 16; o; o >>= 1) s += __shfl_xor_sync(0xffffffffu, s, o);
        if (lane == 0) { if (which) g_t2[gw] = s; else g_x2[gw] = s; }
    } else {
        __nv_bfloat162 z = __floats2bfloat162_rn(0.f, 0.f);
#pragma unroll
        for (int j = 0; j < 4; ++j) {
            dst[(lane + j * 32) * 2 + 0] = z;
            dst[(lane + j * 32) * 2 + 1] = z;
        }
        if (lane == 0 && which) g_t2[gw] = 3.0e38f;
    }
}

// ---------------- mma.sync m16n8k16 bf16 wrapper (portable HMMA) -------------
__device__ __forceinline__ void mma16816(float* c, const uint32_t* a, const uint32_t* b) {
    asm volatile(
        "mma.sync.aligned.m16n8k16.row.col.f32.bf16.bf16.f32 "
        "{%0,%1,%2,%3}, {%4,%5,%6,%7}, {%8,%9}, {%0,%1,%2,%3};"
        : "+f"(c[0]), "+f"(c[1]), "+f"(c[2]), "+f"(c[3])
        : "r"(a[0]), "r"(a[1]), "r"(a[2]), "r"(a[3]), "r"(b[0]), "r"(b[1]));
}

// ---------------- kernel: bf16 HMMA distance GEMM ----------------------------
// d2[q][n] = x2[q] + t2[n] - 2 * dot_bf16(X[q], T[n])   (fp32 accumulate)
// CTA 128x128, BK=32, double-buffered smem, 8 warps: 4(m) x 2(n), warp tile 32x64.
// Grid: x = q-tiles (16, fast) so concurrent CTAs share B tiles via L2.
#define BM 128
#define BN 128
#define BK 32
#define SROW 80                 // padded smem row: 40 bf16 (conflict-free frags)
#define ABYTES (BM * SROW)      // 10240
#define BBYTES (BN * SROW)

__global__ __launch_bounds__(256, 2) void dist_gemm_mma(int N, int Q)
{
    __shared__ __align__(16) char smA[2][ABYTES];
    __shared__ __align__(16) char smB[2][BBYTES];

    const int tid = threadIdx.x;
    const int wid = tid >> 5;
    const int lane = tid & 31;
    const int tq = lane >> 2, tr = lane & 3;
    const int wm = wid & 3, wn = wid >> 2;
    const int bq = blockIdx.x * BM, bn = blockIdx.y * BN;   // q fast, n slow

    // g2s loader mapping: thread -> (row = tid>>2 [+64], seg = tid&3), uint4 = 8 bf16
    const int lrow = tid >> 2;
    const int lseg = tid & 3;
    const int kseg = lseg * 8;                 // bf16 offset in chunk
    const int ssm  = lrow * SROW + lseg * 16;  // smem byte offset (s=0)
    int ar0 = bq + lrow;        if (ar0 > Q - 1) ar0 = Q - 1;
    int ar1 = bq + lrow + 64;   if (ar1 > Q - 1) ar1 = Q - 1;
    const size_t aoff0 = (size_t)ar0 * D_DIM;
    const size_t aoff1 = (size_t)ar1 * D_DIM;
    const size_t boff0 = (size_t)(bn + lrow) * D_DIM;
    const size_t boff1 = (size_t)(bn + lrow + 64) * D_DIM;

    float c[2][8][4];
#pragma unroll
    for (int mi = 0; mi < 2; ++mi)
#pragma unroll
        for (int ni = 0; ni < 8; ++ni)
#pragma unroll
            for (int j = 0; j < 4; ++j) c[mi][ni][j] = 0.f;

    // prologue: chunk 0 -> buffer 0
    {
        uint4 a0 = *reinterpret_cast<const uint4*>(g_xb + aoff0 + kseg);
        uint4 a1 = *reinterpret_cast<const uint4*>(g_xb + aoff1 + kseg);
        uint4 b0 = *reinterpret_cast<const uint4*>(g_tb + boff0 + kseg);
        uint4 b1 = *reinterpret_cast<const uint4*>(g_tb + boff1 + kseg);
        *reinterpret_cast<uint4*>(smA[0] + ssm)             = a0;
        *reinterpret_cast<uint4*>(smA[0] + ssm + 64 * SROW) = a1;
        *reinterpret_cast<uint4*>(smB[0] + ssm)             = b0;
        *reinterpret_cast<uint4*>(smB[0] + ssm + 64 * SROW) = b1;
    }
    __syncthreads();

#pragma unroll 2
    for (int kc = 0; kc < D_DIM / BK; ++kc) {
        uint4 av0, av1, bv0, bv1;
        const bool pre = (kc + 1) < (D_DIM / BK);
        if (pre) {
            const int ko = (kc + 1) * BK + kseg;
            av0 = *reinterpret_cast<const uint4*>(g_xb + aoff0 + ko);
            av1 = *reinterpret_cast<const uint4*>(g_xb + aoff1 + ko);
            bv0 = *reinterpret_cast<const uint4*>(g_tb + boff0 + ko);
            bv1 = *reinterpret_cast<const uint4*>(g_tb + boff1 + ko);
        }
        const char* sA = smA[kc & 1];
        const char* sB = smB[kc & 1];
#pragma unroll
        for (int ks = 0; ks < 2; ++ks) {
            uint32_t a[2][4], b[8][2];
#pragma unroll
            for (int mi = 0; mi < 2; ++mi) {
                const char* p = sA + (wm * 32 + mi * 16 + tq) * SROW + ks * 32 + tr * 4;
                a[mi][0] = *reinterpret_cast<const uint32_t*>(p);
                a[mi][1] = *reinterpret_cast<const uint32_t*>(p + 8 * SROW);
                a[mi][2] = *reinterpret_cast<const uint32_t*>(p + 16);
                a[mi][3] = *reinterpret_cast<const uint32_t*>(p + 8 * SROW + 16);
            }
#pragma unroll
            for (int ni = 0; ni < 8; ++ni) {
                const char* p = sB + (wn * 64 + ni * 8 + tq) * SROW + ks * 32 + tr * 4;
                b[ni][0] = *reinterpret_cast<const uint32_t*>(p);
                b[ni][1] = *reinterpret_cast<const uint32_t*>(p + 16);
            }
#pragma unroll
            for (int mi = 0; mi < 2; ++mi)
#pragma unroll
                for (int ni = 0; ni < 8; ++ni)
                    mma16816(c[mi][ni], a[mi], b[ni]);
        }
        if (pre) {
            char* dA = smA[(kc + 1) & 1];
            char* dB = smB[(kc + 1) & 1];
            *reinterpret_cast<uint4*>(dA + ssm)             = av0;
            *reinterpret_cast<uint4*>(dA + ssm + 64 * SROW) = av1;
            *reinterpret_cast<uint4*>(dB + ssm)             = bv0;
            *reinterpret_cast<uint4*>(dB + ssm + 64 * SROW) = bv1;
        }
        __syncthreads();
    }

    // epilogue: d2 = x2 + t2 - 2*dot
#pragma unroll
    for (int mi = 0; mi < 2; ++mi) {
#pragma unroll
        for (int h = 0; h < 2; ++h) {          // h=0: rows g (c0,c1); h=1: rows g+8 (c2,c3)
            int q = bq + wm * 32 + mi * 16 + tq + h * 8;
            if (q >= Q) continue;
            float qn = g_x2[q];
            float* orow = g_d2 + (size_t)q * N;
#pragma unroll
            for (int ni = 0; ni < 8; ++ni) {
                int n0 = bn + wn * 64 + ni * 8 + tr * 2;
                if (n0 < N) {                   // N even, n0 even -> n0+1 also valid
                    float2 o;
                    o.x = qn + g_t2[n0 + 0] - 2.f * c[mi][ni][h * 2 + 0];
                    o.y = qn + g_t2[n0 + 1] - 2.f * c[mi][ni][h * 2 + 1];
                    *reinterpret_cast<float2*>(orow + n0) = o;
                }
            }
        }
    }
}

// ---------------- kernel: approx top-8/thread -> 64 candidates -> exact rerank
#define TKT 256

// rare-path insertion: kept out-of-line so the hot scan loop stays branchy-cheap
__device__ __noinline__ void insert8(float* bd, int* bi, float vd, int vi) {
#pragma unroll
    for (int j = 0; j < 8; ++j)
        if (vd < bd[j]) { float td = bd[j]; int ti = bi[j];
                          bd[j] = vd; bi[j] = vi; vd = td; vi = ti; }
}

__global__ __launch_bounds__(TKT) void topk_rerank(
    const float* __restrict__ X, const float* __restrict__ T,
    const int* __restrict__ labels, float* __restrict__ out,
    int N, int Q, int out_size)
{
    const int q = blockIdx.x;
    const int tid = threadIdx.x;
    const int lane = tid & 31, wid = tid >> 5;
    const float* row = g_d2 + (size_t)q * N;

    float bd[8]; int bi[8];
#pragma unroll
    for (int j = 0; j < 8; ++j) { bd[j] = 3.4e38f; bi[j] = 0x7fffffff; }
    float thr = 3.4e38f;

    // hot scan: fmin-tree gate per float4; insertion only on (rare) hit
    const float4* row4 = reinterpret_cast<const float4*>(row);
    const int n4 = N >> 2;
    for (int i = tid; i < n4; i += TKT) {
        float4 v = row4[i];
        float m = fminf(fminf(v.x, v.y), fminf(v.z, v.w));
        if (m < thr) {
            int base = i << 2;
            if (v.x < thr) insert8(bd, bi, v.x, base + 0);
            if (v.y < thr) insert8(bd, bi, v.y, base + 1);
            if (v.z < thr) insert8(bd, bi, v.z, base + 2);
            if (v.w < thr) insert8(bd, bi, v.w, base + 3);
            thr = bd[7];
        }
    }
    for (int n = (N & ~3) + tid; n < N; n += TKT) {
        float d = row[n];
        if (d < thr) { insert8(bd, bi, d, n); thr = bd[7]; }
    }

    __shared__ float sd[TKT * 8];
    __shared__ int   si[TKT * 8];
#pragma unroll
    for (int j = 0; j < 8; ++j) { sd[tid * 8 + j] = bd[j]; si[tid * 8 + j] = bi[j]; }
    __syncthreads();

    // stage 1: one thread per warp merges its warp's 256 entries -> warp top-8
    __shared__ float wdv[64];
    __shared__ int   wiv[64];
    if (lane == 0) {
        float md[8]; int mx[8];
#pragma unroll
        for (int j = 0; j < 8; ++j) { md[j] = 3.4e38f; mx[j] = 0x7fffffff; }
        float mthr = 3.4e38f;
        const int base = wid * 256;
        for (int t = 0; t < 256; ++t) {
            float d = sd[base + t];
            if (d < mthr) { insert8(md, mx, d, si[base + t]); mthr = md[7]; }
        }
#pragma unroll
        for (int j = 0; j < 8; ++j) { wdv[wid * 8 + j] = md[j]; wiv[wid * 8 + j] = mx[j]; }
    }
    __syncthreads();

    // exact fp32 rerank of the 64 candidates (warp wid -> candidates wid*8..+7)
    __shared__ float ed[64];
    {
        const float4* x4 = reinterpret_cast<const float4*>(X + (size_t)q * D_DIM);
        float4 xv[4];
#pragma unroll
        for (int j = 0; j < 4; ++j) xv[j] = x4[lane + j * 32];
        for (int cc = 0; cc < 8; ++cc) {
            int idx = wiv[wid * 8 + cc];
            float d2 = 3.4e38f;
            if (idx >= 0 && idx < N) {
                const float4* t4 = reinterpret_cast<const float4*>(T + (size_t)idx * D_DIM);
                float dot = 0.f;
#pragma unroll
                for (int j = 0; j < 4; ++j) {
                    float4 tv = t4[lane + j * 32];
                    dot += xv[j].x * tv.x + xv[j].y * tv.y + xv[j].z * tv.z + xv[j].w * tv.w;
                }
#pragma unroll
                for (int o = 16; o; o >>= 1) dot += __shfl_xor_sync(0xffffffffu, dot, o);
                d2 = g_x2[q] + g_t2[idx] - 2.f * dot;
            }
            if (lane == 0) ed[wid * 8 + cc] = d2;
        }
    }
    __syncthreads();

    // final exact top-5 with (d2, idx) tie-break; write all three output segments
    if (tid == 0) {
        float fd[5]; int fi[5];
#pragma unroll
        for (int j = 0; j < 5; ++j) { fd[j] = 3.4e38f; fi[j] = 0x7fffffff; }
        for (int t = 0; t < 64; ++t) {
            float vd = ed[t]; int vi = wiv[t];
#pragma unroll
            for (int j = 0; j < 5; ++j) {
                bool lt = (vd < fd[j]) || (vd == fd[j] && vi < fi[j]);
                if (lt) { float td = fd[j]; int ti = fi[j];
                          fd[j] = vd; fi[j] = vi; vd = td; vi = ti; }
            }
        }
        const int Q5 = Q * 5;
#pragma unroll
        for (int j = 0; j < 5; ++j) {
            float dist = sqrtf(fmaxf(fd[j], 0.f));
            int idx = fi[j];
            int o0 = q * 5 + j;
            int o1 = Q5 + q * 5 + j;
            int o2 = 2 * Q5 + j * Q + q;
            if (o0 < out_size) out[o0] = dist;
            if (o1 < out_size) out[o1] = (float)idx;
            if (o2 < out_size) out[o2] = (float)labels[idx];
        }
    }
}

// ---------------- launch -----------------------------------------------------
extern "C" void kernel_launch(void* const* d_in, const int* in_sizes, int n_in,
                              void* d_out, int out_size)
{
    const float* X      = (const float*)d_in[0];
    const float* T      = (const float*)d_in[1];
    const int*   labels = (const int*)d_in[2];
    const int Q = in_sizes[0] / D_DIM;
    const int N = in_sizes[2];

    // fused convert + norms (one pass over each matrix); pad T to NPAD with zeros
    convert_norm<<<(Q * 32 + 255) / 256, 256>>>(X, Q, Q, 0);
    convert_norm<<<(NPAD * 32 + 255) / 256, 256>>>(T, N, NPAD, 1);

    // q-tiles on x (fast) so concurrent CTAs reuse each B tile through L2
    dim3 grid((Q + BM - 1) / BM, (N + BN - 1) / BN);
    dist_gemm_mma<<<grid, 256>>>(N, Q);

    topk_rerank<<<Q, TKT>>>(X, T, labels, (float*)d_out, N, Q, out_size);
}

// round 9
// speedup vs baseline: 9.6985x; 9.6985x over previous
#include <cuda_runtime.h>
#include <cuda_bf16.h>
#include <cstdint>

#define D_DIM 512
#define QMAX  2048
#define NPAD  100096   // 782 * 128

// ---------------- scratch (device globals; no allocation allowed) -----------
__device__ __align__(16) float g_d2[(size_t)QMAX * 100000];  // approx d2 (bf16 GEMM)
__device__ float g_x2[QMAX];
__device__ float g_t2[NPAD];
__device__ __align__(256) __nv_bfloat16 g_xb[(size_t)QMAX * D_DIM];
__device__ __align__(256) __nv_bfloat16 g_tb[(size_t)NPAD * D_DIM];

// ---------------- kernel: fused fp32->bf16 convert + row norms --------------
__global__ void convert_norm(const float* __restrict__ src, int rows_valid,
                             int rows_total, int which)
{
    int gw   = (blockIdx.x * blockDim.x + threadIdx.x) >> 5;
    int lane = threadIdx.x & 31;
    if (gw >= rows_total) return;
    __nv_bfloat162* dst =
        reinterpret_cast<__nv_bfloat162*>(which ? g_tb : g_xb) + (size_t)gw * (D_DIM / 2);
    if (gw < rows_valid) {
        const float4* r4 = reinterpret_cast<const float4*>(src + (size_t)gw * D_DIM);
        float s = 0.f;
#pragma unroll
        for (int j = 0; j < 4; ++j) {
            float4 v = r4[lane + j * 32];
            s += v.x * v.x + v.y * v.y + v.z * v.z + v.w * v.w;
            dst[(lane + j * 32) * 2 + 0] = __floats2bfloat162_rn(v.x, v.y);
            dst[(lane + j * 32) * 2 + 1] = __floats2bfloat162_rn(v.z, v.w);
        }
#pragma unroll
        for (int o = 16; o; o >>= 1) s += __shfl_xor_sync(0xffffffffu, s, o);
        if (lane == 0) { if (which) g_t2[gw] = s; else g_x2[gw] = s; }
    } else {
        __nv_bfloat162 z = __floats2bfloat162_rn(0.f, 0.f);
#pragma unroll
        for (int j = 0; j < 4; ++j) {
            dst[(lane + j * 32) * 2 + 0] = z;
            dst[(lane + j * 32) * 2 + 1] = z;
        }
        if (lane == 0 && which) g_t2[gw] = 3.0e38f;
    }
}

// ---------------- mma.sync m16n8k16 bf16 wrapper (portable HMMA) -------------
__device__ __forceinline__ void mma16816(float* c, const uint32_t* a, const uint32_t* b) {
    asm volatile(
        "mma.sync.aligned.m16n8k16.row.col.f32.bf16.bf16.f32 "
        "{%0,%1,%2,%3}, {%4,%5,%6,%7}, {%8,%9}, {%0,%1,%2,%3};"
        : "+f"(c[0]), "+f"(c[1]), "+f"(c[2]), "+f"(c[3])
        : "r"(a[0]), "r"(a[1]), "r"(a[2]), "r"(a[3]), "r"(b[0]), "r"(b[1]));
}

// ---------------- kernel: bf16 HMMA distance GEMM (R7 config, reverted) ------
#define BM 128
#define BN 128
#define BK 32
#define SROW 80                 // padded smem row: 40 bf16 (conflict-free frags)
#define ABYTES (BM * SROW)      // 10240
#define BBYTES (BN * SROW)

__global__ __launch_bounds__(256, 2) void dist_gemm_mma(int N, int Q)
{
    __shared__ __align__(16) char smA[2][ABYTES];
    __shared__ __align__(16) char smB[2][BBYTES];

    const int tid = threadIdx.x;
    const int wid = tid >> 5;
    const int lane = tid & 31;
    const int tq = lane >> 2, tr = lane & 3;
    const int wm = wid & 3, wn = wid >> 2;
    const int bq = blockIdx.y * BM, bn = blockIdx.x * BN;   // R7 raster: n fast

    const int lrow = tid >> 2;
    const int lseg = tid & 3;
    const int kseg = lseg * 8;
    const int ssm  = lrow * SROW + lseg * 16;
    int ar0 = bq + lrow;        if (ar0 > Q - 1) ar0 = Q - 1;
    int ar1 = bq + lrow + 64;   if (ar1 > Q - 1) ar1 = Q - 1;
    const size_t aoff0 = (size_t)ar0 * D_DIM;
    const size_t aoff1 = (size_t)ar1 * D_DIM;
    const size_t boff0 = (size_t)(bn + lrow) * D_DIM;
    const size_t boff1 = (size_t)(bn + lrow + 64) * D_DIM;

    float c[2][8][4];
#pragma unroll
    for (int mi = 0; mi < 2; ++mi)
#pragma unroll
        for (int ni = 0; ni < 8; ++ni)
#pragma unroll
            for (int j = 0; j < 4; ++j) c[mi][ni][j] = 0.f;

    {
        uint4 a0 = *reinterpret_cast<const uint4*>(g_xb + aoff0 + kseg);
        uint4 a1 = *reinterpret_cast<const uint4*>(g_xb + aoff1 + kseg);
        uint4 b0 = *reinterpret_cast<const uint4*>(g_tb + boff0 + kseg);
        uint4 b1 = *reinterpret_cast<const uint4*>(g_tb + boff1 + kseg);
        *reinterpret_cast<uint4*>(smA[0] + ssm)             = a0;
        *reinterpret_cast<uint4*>(smA[0] + ssm + 64 * SROW) = a1;
        *reinterpret_cast<uint4*>(smB[0] + ssm)             = b0;
        *reinterpret_cast<uint4*>(smB[0] + ssm + 64 * SROW) = b1;
    }
    __syncthreads();

#pragma unroll 2
    for (int kc = 0; kc < D_DIM / BK; ++kc) {
        uint4 av0, av1, bv0, bv1;
        const bool pre = (kc + 1) < (D_DIM / BK);
        if (pre) {
            const int ko = (kc + 1) * BK + kseg;
            av0 = *reinterpret_cast<const uint4*>(g_xb + aoff0 + ko);
            av1 = *reinterpret_cast<const uint4*>(g_xb + aoff1 + ko);
            bv0 = *reinterpret_cast<const uint4*>(g_tb + boff0 + ko);
            bv1 = *reinterpret_cast<const uint4*>(g_tb + boff1 + ko);
        }
        const char* sA = smA[kc & 1];
        const char* sB = smB[kc & 1];
#pragma unroll
        for (int ks = 0; ks < 2; ++ks) {
            uint32_t a[2][4], b[8][2];
#pragma unroll
            for (int mi = 0; mi < 2; ++mi) {
                const char* p = sA + (wm * 32 + mi * 16 + tq) * SROW + ks * 32 + tr * 4;
                a[mi][0] = *reinterpret_cast<const uint32_t*>(p);
                a[mi][1] = *reinterpret_cast<const uint32_t*>(p + 8 * SROW);
                a[mi][2] = *reinterpret_cast<const uint32_t*>(p + 16);
                a[mi][3] = *reinterpret_cast<const uint32_t*>(p + 8 * SROW + 16);
            }
#pragma unroll
            for (int ni = 0; ni < 8; ++ni) {
                const char* p = sB + (wn * 64 + ni * 8 + tq) * SROW + ks * 32 + tr * 4;
                b[ni][0] = *reinterpret_cast<const uint32_t*>(p);
                b[ni][1] = *reinterpret_cast<const uint32_t*>(p + 16);
            }
#pragma unroll
            for (int mi = 0; mi < 2; ++mi)
#pragma unroll
                for (int ni = 0; ni < 8; ++ni)
                    mma16816(c[mi][ni], a[mi], b[ni]);
        }
        if (pre) {
            char* dA = smA[(kc + 1) & 1];
            char* dB = smB[(kc + 1) & 1];
            *reinterpret_cast<uint4*>(dA + ssm)             = av0;
            *reinterpret_cast<uint4*>(dA + ssm + 64 * SROW) = av1;
            *reinterpret_cast<uint4*>(dB + ssm)             = bv0;
            *reinterpret_cast<uint4*>(dB + ssm + 64 * SROW) = bv1;
        }
        __syncthreads();
    }

#pragma unroll
    for (int mi = 0; mi < 2; ++mi) {
#pragma unroll
        for (int h = 0; h < 2; ++h) {
            int q = bq + wm * 32 + mi * 16 + tq + h * 8;
            if (q >= Q) continue;
            float qn = g_x2[q];
            float* orow = g_d2 + (size_t)q * N;
#pragma unroll
            for (int ni = 0; ni < 8; ++ni) {
                int n0 = bn + wn * 64 + ni * 8 + tr * 2;
                if (n0 < N) {
                    float2 o;
                    o.x = qn + g_t2[n0 + 0] - 2.f * c[mi][ni][h * 2 + 0];
                    o.y = qn + g_t2[n0 + 1] - 2.f * c[mi][ni][h * 2 + 1];
                    *reinterpret_cast<float2*>(orow + n0) = o;
                }
            }
        }
    }
}

// ---------------- kernel: approx top-8/thread -> 64 candidates -> exact rerank
#define TKT 256

// INLINE insertion: arrays stay in registers (no local-memory demotion)
__device__ __forceinline__ void insert8(float (&bd)[8], int (&bi)[8], float vd, int vi) {
#pragma unroll
    for (int j = 0; j < 8; ++j)
        if (vd < bd[j]) { float td = bd[j]; int ti = bi[j];
                          bd[j] = vd; bi[j] = vi; vd = td; vi = ti; }
}

__global__ __launch_bounds__(TKT) void topk_rerank(
    const float* __restrict__ X, const float* __restrict__ T,
    const int* __restrict__ labels, float* __restrict__ out,
    int N, int Q, int out_size)
{
    const int q = blockIdx.x;
    const int tid = threadIdx.x;
    const int lane = tid & 31, wid = tid >> 5;
    const float* row = g_d2 + (size_t)q * N;

    float bd[8]; int bi[8];
#pragma unroll
    for (int j = 0; j < 8; ++j) { bd[j] = 3.4e38f; bi[j] = 0x7fffffff; }
    float thr = 3.4e38f;

    // hot scan: one fmin-tree gate per float4; large gated body -> real branch
    const float4* row4 = reinterpret_cast<const float4*>(row);
    const int n4 = N >> 2;
    for (int i = tid; i < n4; i += TKT) {
        float4 v = row4[i];
        float m = fminf(fminf(v.x, v.y), fminf(v.z, v.w));
        if (m < thr) {
            int base = i << 2;
            if (v.x < thr) insert8(bd, bi, v.x, base + 0);
            if (v.y < thr) insert8(bd, bi, v.y, base + 1);
            if (v.z < thr) insert8(bd, bi, v.z, base + 2);
            if (v.w < thr) insert8(bd, bi, v.w, base + 3);
            thr = bd[7];
        }
    }
    for (int n = (N & ~3) + tid; n < N; n += TKT) {
        float d = row[n];
        if (d < thr) { insert8(bd, bi, d, n); thr = bd[7]; }
    }

    __shared__ float sd[TKT * 8];
    __shared__ int   si[TKT * 8];
#pragma unroll
    for (int j = 0; j < 8; ++j) { sd[tid * 8 + j] = bd[j]; si[tid * 8 + j] = bi[j]; }
    __syncthreads();

    // stage 1: one thread per warp merges its warp's 256 entries -> warp top-8
    __shared__ float wdv[64];
    __shared__ int   wiv[64];
    if (lane == 0) {
        float md[8]; int mx[8];
#pragma unroll
        for (int j = 0; j < 8; ++j) { md[j] = 3.4e38f; mx[j] = 0x7fffffff; }
        float mthr = 3.4e38f;
        const int base = wid * 256;
        for (int t = 0; t < 256; ++t) {
            float d = sd[base + t];
            if (d < mthr) { insert8(md, mx, d, si[base + t]); mthr = md[7]; }
        }
#pragma unroll
        for (int j = 0; j < 8; ++j) { wdv[wid * 8 + j] = md[j]; wiv[wid * 8 + j] = mx[j]; }
    }
    __syncthreads();

    // exact fp32 rerank of the 64 candidates (warp wid -> candidates wid*8..+7)
    __shared__ float ed[64];
    {
        const float4* x4 = reinterpret_cast<const float4*>(X + (size_t)q * D_DIM);
        float4 xv[4];
#pragma unroll
        for (int j = 0; j < 4; ++j) xv[j] = x4[lane + j * 32];
        for (int cc = 0; cc < 8; ++cc) {
            int idx = wiv[wid * 8 + cc];
            float d2 = 3.4e38f;
            if (idx >= 0 && idx < N) {
                const float4* t4 = reinterpret_cast<const float4*>(T + (size_t)idx * D_DIM);
                float dot = 0.f;
#pragma unroll
                for (int j = 0; j < 4; ++j) {
                    float4 tv = t4[lane + j * 32];
                    dot += xv[j].x * tv.x + xv[j].y * tv.y + xv[j].z * tv.z + xv[j].w * tv.w;
                }
#pragma unroll
                for (int o = 16; o; o >>= 1) dot += __shfl_xor_sync(0xffffffffu, dot, o);
                d2 = g_x2[q] + g_t2[idx] - 2.f * dot;
            }
            if (lane == 0) ed[wid * 8 + cc] = d2;
        }
    }
    __syncthreads();

    // final exact top-5 with (d2, idx) tie-break; write all three output segments
    if (tid == 0) {
        float fd[5]; int fi[5];
#pragma unroll
        for (int j = 0; j < 5; ++j) { fd[j] = 3.4e38f; fi[j] = 0x7fffffff; }
        for (int t = 0; t < 64; ++t) {
            float vd = ed[t]; int vi = wiv[t];
#pragma unroll
            for (int j = 0; j < 5; ++j) {
                bool lt = (vd < fd[j]) || (vd == fd[j] && vi < fi[j]);
                if (lt) { float td = fd[j]; int ti = fi[j];
                          fd[j] = vd; fi[j] = vi; vd = td; vi = ti; }
            }
        }
        const int Q5 = Q * 5;
#pragma unroll
        for (int j = 0; j < 5; ++j) {
            float dist = sqrtf(fmaxf(fd[j], 0.f));
            int idx = fi[j];
            int o0 = q * 5 + j;
            int o1 = Q5 + q * 5 + j;
            int o2 = 2 * Q5 + j * Q + q;
            if (o0 < out_size) out[o0] = dist;
            if (o1 < out_size) out[o1] = (float)idx;
            if (o2 < out_size) out[o2] = (float)labels[idx];
        }
    }
}

// ---------------- launch -----------------------------------------------------
extern "C" void kernel_launch(void* const* d_in, const int* in_sizes, int n_in,
                              void* d_out, int out_size)
{
    const float* X      = (const float*)d_in[0];
    const float* T      = (const float*)d_in[1];
    const int*   labels = (const int*)d_in[2];
    const int Q = in_sizes[0] / D_DIM;
    const int N = in_sizes[2];

    convert_norm<<<(Q * 32 + 255) / 256, 256>>>(X, Q, Q, 0);
    convert_norm<<<(NPAD * 32 + 255) / 256, 256>>>(T, N, NPAD, 1);

    // R7 raster: n-tiles on x (fast)
    dim3 grid((N + BN - 1) / BN, (Q + BM - 1) / BM);
    dist_gemm_mma<<<grid, 256>>>(N, Q);

    topk_rerank<<<Q, TKT>>>(X, T, labels, (float*)d_out, N, Q, out_size);
}

// round 10
// speedup vs baseline: 11.6541x; 1.2016x over previous
#include <cuda_runtime.h>
#include <cuda_bf16.h>
#include <cstdint>

#define D_DIM 512
#define QMAX  2048
#define NPAD  100096   // 782 * 128

// ---------------- scratch (device globals; no allocation allowed) -----------
__device__ __align__(16) float g_d2[(size_t)QMAX * 100000];  // approx d2 (bf16 GEMM)
__device__ float g_x2[QMAX];
__device__ float g_t2[NPAD];
__device__ __align__(256) __nv_bfloat16 g_xb[(size_t)QMAX * D_DIM];
__device__ __align__(256) __nv_bfloat16 g_tb[(size_t)NPAD * D_DIM];

// ---------------- kernel: fused fp32->bf16 convert + row norms --------------
__global__ void convert_norm(const float* __restrict__ src, int rows_valid,
                             int rows_total, int which)
{
    int gw   = (blockIdx.x * blockDim.x + threadIdx.x) >> 5;
    int lane = threadIdx.x & 31;
    if (gw >= rows_total) return;
    __nv_bfloat162* dst =
        reinterpret_cast<__nv_bfloat162*>(which ? g_tb : g_xb) + (size_t)gw * (D_DIM / 2);
    if (gw < rows_valid) {
        const float4* r4 = reinterpret_cast<const float4*>(src + (size_t)gw * D_DIM);
        float s = 0.f;
#pragma unroll
        for (int j = 0; j < 4; ++j) {
            float4 v = r4[lane + j * 32];
            s += v.x * v.x + v.y * v.y + v.z * v.z + v.w * v.w;
            dst[(lane + j * 32) * 2 + 0] = __floats2bfloat162_rn(v.x, v.y);
            dst[(lane + j * 32) * 2 + 1] = __floats2bfloat162_rn(v.z, v.w);
        }
#pragma unroll
        for (int o = 16; o; o >>= 1) s += __shfl_xor_sync(0xffffffffu, s, o);
        if (lane == 0) { if (which) g_t2[gw] = s; else g_x2[gw] = s; }
    } else {
        __nv_bfloat162 z = __floats2bfloat162_rn(0.f, 0.f);
#pragma unroll
        for (int j = 0; j < 4; ++j) {
            dst[(lane + j * 32) * 2 + 0] = z;
            dst[(lane + j * 32) * 2 + 1] = z;
        }
        if (lane == 0 && which) g_t2[gw] = 3.0e38f;
    }
}

// ---------------- mma.sync m16n8k16 bf16 wrapper (portable HMMA) -------------
__device__ __forceinline__ void mma16816(float* c, const uint32_t* a, const uint32_t* b) {
    asm volatile(
        "mma.sync.aligned.m16n8k16.row.col.f32.bf16.bf16.f32 "
        "{%0,%1,%2,%3}, {%4,%5,%6,%7}, {%8,%9}, {%0,%1,%2,%3};"
        : "+f"(c[0]), "+f"(c[1]), "+f"(c[2]), "+f"(c[3])
        : "r"(a[0]), "r"(a[1]), "r"(a[2]), "r"(a[3]), "r"(b[0]), "r"(b[1]));
}

// ---------------- kernel: bf16 HMMA distance GEMM (R7 config, unchanged) -----
#define BM 128
#define BN 128
#define BK 32
#define SROW 80
#define ABYTES (BM * SROW)
#define BBYTES (BN * SROW)

__global__ __launch_bounds__(256, 2) void dist_gemm_mma(int N, int Q)
{
    __shared__ __align__(16) char smA[2][ABYTES];
    __shared__ __align__(16) char smB[2][BBYTES];

    const int tid = threadIdx.x;
    const int wid = tid >> 5;
    const int lane = tid & 31;
    const int tq = lane >> 2, tr = lane & 3;
    const int wm = wid & 3, wn = wid >> 2;
    const int bq = blockIdx.y * BM, bn = blockIdx.x * BN;

    const int lrow = tid >> 2;
    const int lseg = tid & 3;
    const int kseg = lseg * 8;
    const int ssm  = lrow * SROW + lseg * 16;
    int ar0 = bq + lrow;        if (ar0 > Q - 1) ar0 = Q - 1;
    int ar1 = bq + lrow + 64;   if (ar1 > Q - 1) ar1 = Q - 1;
    const size_t aoff0 = (size_t)ar0 * D_DIM;
    const size_t aoff1 = (size_t)ar1 * D_DIM;
    const size_t boff0 = (size_t)(bn + lrow) * D_DIM;
    const size_t boff1 = (size_t)(bn + lrow + 64) * D_DIM;

    float c[2][8][4];
#pragma unroll
    for (int mi = 0; mi < 2; ++mi)
#pragma unroll
        for (int ni = 0; ni < 8; ++ni)
#pragma unroll
            for (int j = 0; j < 4; ++j) c[mi][ni][j] = 0.f;

    {
        uint4 a0 = *reinterpret_cast<const uint4*>(g_xb + aoff0 + kseg);
        uint4 a1 = *reinterpret_cast<const uint4*>(g_xb + aoff1 + kseg);
        uint4 b0 = *reinterpret_cast<const uint4*>(g_tb + boff0 + kseg);
        uint4 b1 = *reinterpret_cast<const uint4*>(g_tb + boff1 + kseg);
        *reinterpret_cast<uint4*>(smA[0] + ssm)             = a0;
        *reinterpret_cast<uint4*>(smA[0] + ssm + 64 * SROW) = a1;
        *reinterpret_cast<uint4*>(smB[0] + ssm)             = b0;
        *reinterpret_cast<uint4*>(smB[0] + ssm + 64 * SROW) = b1;
    }
    __syncthreads();

#pragma unroll 2
    for (int kc = 0; kc < D_DIM / BK; ++kc) {
        uint4 av0, av1, bv0, bv1;
        const bool pre = (kc + 1) < (D_DIM / BK);
        if (pre) {
            const int ko = (kc + 1) * BK + kseg;
            av0 = *reinterpret_cast<const uint4*>(g_xb + aoff0 + ko);
            av1 = *reinterpret_cast<const uint4*>(g_xb + aoff1 + ko);
            bv0 = *reinterpret_cast<const uint4*>(g_tb + boff0 + ko);
            bv1 = *reinterpret_cast<const uint4*>(g_tb + boff1 + ko);
        }
        const char* sA = smA[kc & 1];
        const char* sB = smB[kc & 1];
#pragma unroll
        for (int ks = 0; ks < 2; ++ks) {
            uint32_t a[2][4], b[8][2];
#pragma unroll
            for (int mi = 0; mi < 2; ++mi) {
                const char* p = sA + (wm * 32 + mi * 16 + tq) * SROW + ks * 32 + tr * 4;
                a[mi][0] = *reinterpret_cast<const uint32_t*>(p);
                a[mi][1] = *reinterpret_cast<const uint32_t*>(p + 8 * SROW);
                a[mi][2] = *reinterpret_cast<const uint32_t*>(p + 16);
                a[mi][3] = *reinterpret_cast<const uint32_t*>(p + 8 * SROW + 16);
            }
#pragma unroll
            for (int ni = 0; ni < 8; ++ni) {
                const char* p = sB + (wn * 64 + ni * 8 + tq) * SROW + ks * 32 + tr * 4;
                b[ni][0] = *reinterpret_cast<const uint32_t*>(p);
                b[ni][1] = *reinterpret_cast<const uint32_t*>(p + 16);
            }
#pragma unroll
            for (int mi = 0; mi < 2; ++mi)
#pragma unroll
                for (int ni = 0; ni < 8; ++ni)
                    mma16816(c[mi][ni], a[mi], b[ni]);
        }
        if (pre) {
            char* dA = smA[(kc + 1) & 1];
            char* dB = smB[(kc + 1) & 1];
            *reinterpret_cast<uint4*>(dA + ssm)             = av0;
            *reinterpret_cast<uint4*>(dA + ssm + 64 * SROW) = av1;
            *reinterpret_cast<uint4*>(dB + ssm)             = bv0;
            *reinterpret_cast<uint4*>(dB + ssm + 64 * SROW) = bv1;
        }
        __syncthreads();
    }

#pragma unroll
    for (int mi = 0; mi < 2; ++mi) {
#pragma unroll
        for (int h = 0; h < 2; ++h) {
            int q = bq + wm * 32 + mi * 16 + tq + h * 8;
            if (q >= Q) continue;
            float qn = g_x2[q];
            float* orow = g_d2 + (size_t)q * N;
#pragma unroll
            for (int ni = 0; ni < 8; ++ni) {
                int n0 = bn + wn * 64 + ni * 8 + tr * 2;
                if (n0 < N) {
                    float2 o;
                    o.x = qn + g_t2[n0 + 0] - 2.f * c[mi][ni][h * 2 + 0];
                    o.y = qn + g_t2[n0 + 1] - 2.f * c[mi][ni][h * 2 + 1];
                    *reinterpret_cast<float2*>(orow + n0) = o;
                }
            }
        }
    }
}

// ---------------- topk: branch-free per-thread top-3 -> 64 cand -> rerank ----
#define TKT 256

// predicated compare-swap: enforce (ad,ai) <= (bd,bi)
__device__ __forceinline__ void cswap(float& ad, int& ai, float& bd, int& bi) {
    bool s = bd < ad;
    float t0 = s ? bd : ad;  float t1 = s ? ad : bd;
    int   u0 = s ? bi : ai;  int   u1 = s ? ai : bi;
    ad = t0; ai = u0; bd = t1; bi = u1;
}
// branch-free insert into sorted triple (b0<=b1<=b2)
__device__ __forceinline__ void ins3(float& b0d, int& b0i, float& b1d, int& b1i,
                                     float& b2d, int& b2i, float d, int n) {
    bool p = d < b2d;
    b2d = p ? d : b2d;  b2i = p ? n : b2i;
    cswap(b1d, b1i, b2d, b2i);
    cswap(b0d, b0i, b1d, b1i);
}

// gated full insert for the (rare-path) warp merge stage
__device__ __forceinline__ void insert8(float (&bd)[8], int (&bi)[8], float vd, int vi) {
#pragma unroll
    for (int j = 0; j < 8; ++j)
        if (vd < bd[j]) { float td = bd[j]; int ti = bi[j];
                          bd[j] = vd; bi[j] = vi; vd = td; vi = ti; }
}

__global__ __launch_bounds__(TKT) void topk_rerank(
    const float* __restrict__ X, const float* __restrict__ T,
    const int* __restrict__ labels, float* __restrict__ out,
    int N, int Q, int out_size)
{
    const int q = blockIdx.x;
    const int tid = threadIdx.x;
    const int lane = tid & 31, wid = tid >> 5;
    const float* row = g_d2 + (size_t)q * N;

    float b0d = 3.4e38f, b1d = 3.4e38f, b2d = 3.4e38f;
    int   b0i = 0x7fffffff, b1i = 0x7fffffff, b2i = 0x7fffffff;

    // hot scan: fully predicated top-3 maintenance, zero divergence
    const float4* row4 = reinterpret_cast<const float4*>(row);
    const int n4 = N >> 2;
    for (int i = tid; i < n4; i += TKT) {
        float4 v = row4[i];
        int base = i << 2;
        ins3(b0d, b0i, b1d, b1i, b2d, b2i, v.x, base + 0);
        ins3(b0d, b0i, b1d, b1i, b2d, b2i, v.y, base + 1);
        ins3(b0d, b0i, b1d, b1i, b2d, b2i, v.z, base + 2);
        ins3(b0d, b0i, b1d, b1i, b2d, b2i, v.w, base + 3);
    }
    for (int n = (N & ~3) + tid; n < N; n += TKT) {
        ins3(b0d, b0i, b1d, b1i, b2d, b2i, row[n], n);
    }

    __shared__ float sd[TKT * 3];
    __shared__ int   si[TKT * 3];
    sd[tid * 3 + 0] = b0d; si[tid * 3 + 0] = b0i;
    sd[tid * 3 + 1] = b1d; si[tid * 3 + 1] = b1i;
    sd[tid * 3 + 2] = b2d; si[tid * 3 + 2] = b2i;
    __syncthreads();

    // stage 1: lane0 of each warp merges its warp's 96 entries -> warp top-8
    __shared__ float wdv[64];
    __shared__ int   wiv[64];
    if (lane == 0) {
        float md[8]; int mx[8];
#pragma unroll
        for (int j = 0; j < 8; ++j) { md[j] = 3.4e38f; mx[j] = 0x7fffffff; }
        float mthr = 3.4e38f;
        const int base = wid * 96;
        for (int t = 0; t < 96; ++t) {
            float d = sd[base + t];
            if (d < mthr) { insert8(md, mx, d, si[base + t]); mthr = md[7]; }
        }
#pragma unroll
        for (int j = 0; j < 8; ++j) { wdv[wid * 8 + j] = md[j]; wiv[wid * 8 + j] = mx[j]; }
    }
    __syncthreads();

    // exact fp32 rerank of the 64 candidates (warp wid -> candidates wid*8..+7)
    __shared__ float ed[64];
    {
        const float4* x4 = reinterpret_cast<const float4*>(X + (size_t)q * D_DIM);
        float4 xv[4];
#pragma unroll
        for (int j = 0; j < 4; ++j) xv[j] = x4[lane + j * 32];
        for (int cc = 0; cc < 8; ++cc) {
            int idx = wiv[wid * 8 + cc];
            float d2 = 3.4e38f;
            if (idx >= 0 && idx < N) {
                const float4* t4 = reinterpret_cast<const float4*>(T + (size_t)idx * D_DIM);
                float dot = 0.f;
#pragma unroll
                for (int j = 0; j < 4; ++j) {
                    float4 tv = t4[lane + j * 32];
                    dot += xv[j].x * tv.x + xv[j].y * tv.y + xv[j].z * tv.z + xv[j].w * tv.w;
                }
#pragma unroll
                for (int o = 16; o; o >>= 1) dot += __shfl_xor_sync(0xffffffffu, dot, o);
                d2 = g_x2[q] + g_t2[idx] - 2.f * dot;
            }
            if (lane == 0) ed[wid * 8 + cc] = d2;
        }
    }
    __syncthreads();

    // final exact top-5 with (d2, idx) tie-break; write all three output segments
    if (tid == 0) {
        float fd[5]; int fi[5];
#pragma unroll
        for (int j = 0; j < 5; ++j) { fd[j] = 3.4e38f; fi[j] = 0x7fffffff; }
        for (int t = 0; t < 64; ++t) {
            float vd = ed[t]; int vi = wiv[t];
#pragma unroll
            for (int j = 0; j < 5; ++j) {
                bool lt = (vd < fd[j]) || (vd == fd[j] && vi < fi[j]);
                if (lt) { float td = fd[j]; int ti = fi[j];
                          fd[j] = vd; fi[j] = vi; vd = td; vi = ti; }
            }
        }
        const int Q5 = Q * 5;
#pragma unroll
        for (int j = 0; j < 5; ++j) {
            float dist = sqrtf(fmaxf(fd[j], 0.f));
            int idx = fi[j];
            int o0 = q * 5 + j;
            int o1 = Q5 + q * 5 + j;
            int o2 = 2 * Q5 + j * Q + q;
            if (o0 < out_size) out[o0] = dist;
            if (o1 < out_size) out[o1] = (float)idx;
            if (o2 < out_size) out[o2] = (float)labels[idx];
        }
    }
}

// ---------------- launch -----------------------------------------------------
extern "C" void kernel_launch(void* const* d_in, const int* in_sizes, int n_in,
                              void* d_out, int out_size)
{
    const float* X      = (const float*)d_in[0];
    const float* T      = (const float*)d_in[1];
    const int*   labels = (const int*)d_in[2];
    const int Q = in_sizes[0] / D_DIM;
    const int N = in_sizes[2];

    convert_norm<<<(Q * 32 + 255) / 256, 256>>>(X, Q, Q, 0);
    convert_norm<<<(NPAD * 32 + 255) / 256, 256>>>(T, N, NPAD, 1);

    dim3 grid((N + BN - 1) / BN, (Q + BM - 1) / BM);
    dist_gemm_mma<<<grid, 256>>>(N, Q);

    topk_rerank<<<Q, TKT>>>(X, T, labels, (float*)d_out, N, Q, out_size);
}

// round 11
// speedup vs baseline: 13.0181x; 1.1170x over previous
#include <cuda_runtime.h>
#include <cuda_bf16.h>
#include <cuda_fp16.h>
#include <cstdint>

#define D_DIM 512
#define QMAX  2048
#define NPAD  100096   // 782 * 128

// ---------------- scratch (device globals; no allocation allowed) -----------
__device__ __align__(16) __half g_s[(size_t)QMAX * 100000];  // fp16 score t2-2dot
__device__ float g_x2[QMAX];
__device__ float g_t2[NPAD];
__device__ __align__(256) __nv_bfloat16 g_xb[(size_t)QMAX * D_DIM];
__device__ __align__(256) __nv_bfloat16 g_tb[(size_t)NPAD * D_DIM];

// ---------------- helpers ----------------------------------------------------
__device__ __forceinline__ uint32_t smem_u32(const void* p) {
    uint32_t a;
    asm("{ .reg .u64 t; cvta.to.shared.u64 t, %1; cvt.u32.u64 %0, t; }" : "=r"(a) : "l"(p));
    return a;
}
__device__ __forceinline__ void cpasync16(uint32_t saddr, const void* g) {
    asm volatile("cp.async.cg.shared.global [%0], [%1], 16;"
                 :: "r"(saddr), "l"(__cvta_generic_to_global(g)) : "memory");
}
#define CP_COMMIT() asm volatile("cp.async.commit_group;" ::: "memory")
#define CP_WAIT0()  asm volatile("cp.async.wait_group 0;" ::: "memory")

// ---------------- kernel: fused fp32->bf16 convert + row norms --------------
__global__ void convert_norm(const float* __restrict__ src, int rows_valid,
                             int rows_total, int which)
{
    int gw   = (blockIdx.x * blockDim.x + threadIdx.x) >> 5;
    int lane = threadIdx.x & 31;
    if (gw >= rows_total) return;
    __nv_bfloat162* dst =
        reinterpret_cast<__nv_bfloat162*>(which ? g_tb : g_xb) + (size_t)gw * (D_DIM / 2);
    if (gw < rows_valid) {
        const float4* r4 = reinterpret_cast<const float4*>(src + (size_t)gw * D_DIM);
        float s = 0.f;
#pragma unroll
        for (int j = 0; j < 4; ++j) {
            float4 v = r4[lane + j * 32];
            s += v.x * v.x + v.y * v.y + v.z * v.z + v.w * v.w;
            dst[(lane + j * 32) * 2 + 0] = __floats2bfloat162_rn(v.x, v.y);
            dst[(lane + j * 32) * 2 + 1] = __floats2bfloat162_rn(v.z, v.w);
        }
#pragma unroll
        for (int o = 16; o; o >>= 1) s += __shfl_xor_sync(0xffffffffu, s, o);
        if (lane == 0) { if (which) g_t2[gw] = s; else g_x2[gw] = s; }
    } else {
        __nv_bfloat162 z = __floats2bfloat162_rn(0.f, 0.f);
#pragma unroll
        for (int j = 0; j < 4; ++j) {
            dst[(lane + j * 32) * 2 + 0] = z;
            dst[(lane + j * 32) * 2 + 1] = z;
        }
        if (lane == 0 && which) g_t2[gw] = 3.0e38f;
    }
}

// ---------------- mma.sync m16n8k16 bf16 wrapper (portable HMMA) -------------
__device__ __forceinline__ void mma16816(float* c, const uint32_t* a, const uint32_t* b) {
    asm volatile(
        "mma.sync.aligned.m16n8k16.row.col.f32.bf16.bf16.f32 "
        "{%0,%1,%2,%3}, {%4,%5,%6,%7}, {%8,%9}, {%0,%1,%2,%3};"
        : "+f"(c[0]), "+f"(c[1]), "+f"(c[2]), "+f"(c[3])
        : "r"(a[0]), "r"(a[1]), "r"(a[2]), "r"(a[3]), "r"(b[0]), "r"(b[1]));
}

// ---------------- kernel: bf16 HMMA distance GEMM, cp.async pipeline ---------
// s[q][n] = t2[n] - 2 * dot_bf16(X[q], T[n])  stored as fp16
#define BM 128
#define BN 128
#define BK 32
#define SROW 80
#define ABYTES (BM * SROW)
#define BBYTES (BN * SROW)

__global__ __launch_bounds__(256, 2) void dist_gemm_mma(int N, int Q)
{
    __shared__ __align__(16) char smA[2][ABYTES];
    __shared__ __align__(16) char smB[2][BBYTES];

    const int tid = threadIdx.x;
    const int wid = tid >> 5;
    const int lane = tid & 31;
    const int tq = lane >> 2, tr = lane & 3;
    const int wm = wid & 3, wn = wid >> 2;
    const int bq = blockIdx.y * BM, bn = blockIdx.x * BN;   // n fast (R7 raster)

    const int lrow = tid >> 2;
    const int lseg = tid & 3;
    const int kseg = lseg * 8;
    const int ssm  = lrow * SROW + lseg * 16;   // 16B-aligned (80 = 5*16)
    int ar0 = bq + lrow;        if (ar0 > Q - 1) ar0 = Q - 1;
    int ar1 = bq + lrow + 64;   if (ar1 > Q - 1) ar1 = Q - 1;
    const size_t aoff0 = (size_t)ar0 * D_DIM;
    const size_t aoff1 = (size_t)ar1 * D_DIM;
    const size_t boff0 = (size_t)(bn + lrow) * D_DIM;
    const size_t boff1 = (size_t)(bn + lrow + 64) * D_DIM;

    const uint32_t sa[2] = { smem_u32(smA[0]) + ssm, smem_u32(smA[1]) + ssm };
    const uint32_t sb[2] = { smem_u32(smB[0]) + ssm, smem_u32(smB[1]) + ssm };

    float c[2][8][4];
#pragma unroll
    for (int mi = 0; mi < 2; ++mi)
#pragma unroll
        for (int ni = 0; ni < 8; ++ni)
#pragma unroll
            for (int j = 0; j < 4; ++j) c[mi][ni][j] = 0.f;

    // prologue: async-load chunk 0 into buffer 0
    cpasync16(sa[0],             g_xb + aoff0 + kseg);
    cpasync16(sa[0] + 64 * SROW, g_xb + aoff1 + kseg);
    cpasync16(sb[0],             g_tb + boff0 + kseg);
    cpasync16(sb[0] + 64 * SROW, g_tb + boff1 + kseg);
    CP_COMMIT();
    CP_WAIT0();
    __syncthreads();

#pragma unroll 2
    for (int kc = 0; kc < D_DIM / BK; ++kc) {
        const bool pre = (kc + 1) < (D_DIM / BK);
        if (pre) {  // issue next-buffer loads before compute; they overlap MMA
            const int ko = (kc + 1) * BK + kseg;
            const int nb = (kc + 1) & 1;
            cpasync16(sa[nb],             g_xb + aoff0 + ko);
            cpasync16(sa[nb] + 64 * SROW, g_xb + aoff1 + ko);
            cpasync16(sb[nb],             g_tb + boff0 + ko);
            cpasync16(sb[nb] + 64 * SROW, g_tb + boff1 + ko);
            CP_COMMIT();
        }
        const char* sA = smA[kc & 1];
        const char* sB = smB[kc & 1];
#pragma unroll
        for (int ks = 0; ks < 2; ++ks) {
            uint32_t a[2][4], b[8][2];
#pragma unroll
            for (int mi = 0; mi < 2; ++mi) {
                const char* p = sA + (wm * 32 + mi * 16 + tq) * SROW + ks * 32 + tr * 4;
                a[mi][0] = *reinterpret_cast<const uint32_t*>(p);
                a[mi][1] = *reinterpret_cast<const uint32_t*>(p + 8 * SROW);
                a[mi][2] = *reinterpret_cast<const uint32_t*>(p + 16);
                a[mi][3] = *reinterpret_cast<const uint32_t*>(p + 8 * SROW + 16);
            }
#pragma unroll
            for (int ni = 0; ni < 8; ++ni) {
                const char* p = sB + (wn * 64 + ni * 8 + tq) * SROW + ks * 32 + tr * 4;
                b[ni][0] = *reinterpret_cast<const uint32_t*>(p);
                b[ni][1] = *reinterpret_cast<const uint32_t*>(p + 16);
            }
#pragma unroll
            for (int mi = 0; mi < 2; ++mi)
#pragma unroll
                for (int ni = 0; ni < 8; ++ni)
                    mma16816(c[mi][ni], a[mi], b[ni]);
        }
        if (pre) {
            CP_WAIT0();
            __syncthreads();
        }
    }

    // epilogue: s = t2 - 2*dot, fp16 store (row constant x2 dropped: rank-invariant)
#pragma unroll
    for (int mi = 0; mi < 2; ++mi) {
#pragma unroll
        for (int h = 0; h < 2; ++h) {
            int q = bq + wm * 32 + mi * 16 + tq + h * 8;
            if (q >= Q) continue;
            __half* srow = g_s + (size_t)q * N;
#pragma unroll
            for (int ni = 0; ni < 8; ++ni) {
                int n0 = bn + wn * 64 + ni * 8 + tr * 2;
                if (n0 < N) {
                    float sx = g_t2[n0 + 0] - 2.f * c[mi][ni][h * 2 + 0];
                    float sy = g_t2[n0 + 1] - 2.f * c[mi][ni][h * 2 + 1];
                    *reinterpret_cast<__half2*>(srow + n0) = __floats2half2_rn(sx, sy);
                }
            }
        }
    }
}

// ---------------- topk: branch-free per-thread top-3 on fp16 scores ----------
#define TKT 256

__device__ __forceinline__ void cswap(float& ad, int& ai, float& bd, int& bi) {
    bool s = bd < ad;
    float t0 = s ? bd : ad;  float t1 = s ? ad : bd;
    int   u0 = s ? bi : ai;  int   u1 = s ? ai : bi;
    ad = t0; ai = u0; bd = t1; bi = u1;
}
__device__ __forceinline__ void ins3(float& b0d, int& b0i, float& b1d, int& b1i,
                                     float& b2d, int& b2i, float d, int n) {
    bool p = d < b2d;
    b2d = p ? d : b2d;  b2i = p ? n : b2i;
    cswap(b1d, b1i, b2d, b2i);
    cswap(b0d, b0i, b1d, b1i);
}
__device__ __forceinline__ void insert8(float (&bd)[8], int (&bi)[8], float vd, int vi) {
#pragma unroll
    for (int j = 0; j < 8; ++j)
        if (vd < bd[j]) { float td = bd[j]; int ti = bi[j];
                          bd[j] = vd; bi[j] = vi; vd = td; vi = ti; }
}

__global__ __launch_bounds__(TKT) void topk_rerank(
    const float* __restrict__ X, const float* __restrict__ T,
    const int* __restrict__ labels, float* __restrict__ out,
    int N, int Q, int out_size)
{
    const int q = blockIdx.x;
    const int tid = threadIdx.x;
    const int lane = tid & 31, wid = tid >> 5;
    const __half* row = g_s + (size_t)q * N;

    float b0d = 3.4e38f, b1d = 3.4e38f, b2d = 3.4e38f;
    int   b0i = 0x7fffffff, b1i = 0x7fffffff, b2i = 0x7fffffff;

    // hot scan: uint4 = 8 fp16 scores; N % 8 == 0 so no tail
    const uint4* row8 = reinterpret_cast<const uint4*>(row);
    const int n8 = N >> 3;
    for (int i = tid; i < n8; i += TKT) {
        uint4 v = row8[i];
        int base = i << 3;
        float2 f0 = __half22float2(*reinterpret_cast<__half2*>(&v.x));
        float2 f1 = __half22float2(*reinterpret_cast<__half2*>(&v.y));
        float2 f2 = __half22float2(*reinterpret_cast<__half2*>(&v.z));
        float2 f3 = __half22float2(*reinterpret_cast<__half2*>(&v.w));
        ins3(b0d, b0i, b1d, b1i, b2d, b2i, f0.x, base + 0);
        ins3(b0d, b0i, b1d, b1i, b2d, b2i, f0.y, base + 1);
        ins3(b0d, b0i, b1d, b1i, b2d, b2i, f1.x, base + 2);
        ins3(b0d, b0i, b1d, b1i, b2d, b2i, f1.y, base + 3);
        ins3(b0d, b0i, b1d, b1i, b2d, b2i, f2.x, base + 4);
        ins3(b0d, b0i, b1d, b1i, b2d, b2i, f2.y, base + 5);
        ins3(b0d, b0i, b1d, b1i, b2d, b2i, f3.x, base + 6);
        ins3(b0d, b0i, b1d, b1i, b2d, b2i, f3.y, base + 7);
    }

    __shared__ float sd[TKT * 3];
    __shared__ int   si[TKT * 3];
    sd[tid * 3 + 0] = b0d; si[tid * 3 + 0] = b0i;
    sd[tid * 3 + 1] = b1d; si[tid * 3 + 1] = b1i;
    sd[tid * 3 + 2] = b2d; si[tid * 3 + 2] = b2i;
    __syncthreads();

    // stage 1: lane0 of each warp merges its warp's 96 entries -> warp top-8
    __shared__ float wdv[64];
    __shared__ int   wiv[64];
    if (lane == 0) {
        float md[8]; int mx[8];
#pragma unroll
        for (int j = 0; j < 8; ++j) { md[j] = 3.4e38f; mx[j] = 0x7fffffff; }
        float mthr = 3.4e38f;
        const int base = wid * 96;
        for (int t = 0; t < 96; ++t) {
            float d = sd[base + t];
            if (d < mthr) { insert8(md, mx, d, si[base + t]); mthr = md[7]; }
        }
#pragma unroll
        for (int j = 0; j < 8; ++j) { wdv[wid * 8 + j] = md[j]; wiv[wid * 8 + j] = mx[j]; }
    }
    __syncthreads();

    // exact fp32 rerank of the 64 candidates (warp wid -> candidates wid*8..+7)
    __shared__ float ed[64];
    {
        const float4* x4 = reinterpret_cast<const float4*>(X + (size_t)q * D_DIM);
        float4 xv[4];
#pragma unroll
        for (int j = 0; j < 4; ++j) xv[j] = x4[lane + j * 32];
        for (int cc = 0; cc < 8; ++cc) {
            int idx = wiv[wid * 8 + cc];
            float d2 = 3.4e38f;
            if (idx >= 0 && idx < N) {
                const float4* t4 = reinterpret_cast<const float4*>(T + (size_t)idx * D_DIM);
                float dot = 0.f;
#pragma unroll
                for (int j = 0; j < 4; ++j) {
                    float4 tv = t4[lane + j * 32];
                    dot += xv[j].x * tv.x + xv[j].y * tv.y + xv[j].z * tv.z + xv[j].w * tv.w;
                }
#pragma unroll
                for (int o = 16; o; o >>= 1) dot += __shfl_xor_sync(0xffffffffu, dot, o);
                d2 = g_x2[q] + g_t2[idx] - 2.f * dot;
            }
            if (lane == 0) ed[wid * 8 + cc] = d2;
        }
    }
    __syncthreads();

    // final exact top-5 with (d2, idx) tie-break; write all three output segments
    if (tid == 0) {
        float fd[5]; int fi[5];
#pragma unroll
        for (int j = 0; j < 5; ++j) { fd[j] = 3.4e38f; fi[j] = 0x7fffffff; }
        for (int t = 0; t < 64; ++t) {
            float vd = ed[t]; int vi = wiv[t];
#pragma unroll
            for (int j = 0; j < 5; ++j) {
                bool lt = (vd < fd[j]) || (vd == fd[j] && vi < fi[j]);
                if (lt) { float td = fd[j]; int ti = fi[j];
                          fd[j] = vd; fi[j] = vi; vd = td; vi = ti; }
            }
        }
        const int Q5 = Q * 5;
#pragma unroll
        for (int j = 0; j < 5; ++j) {
            float dist = sqrtf(fmaxf(fd[j], 0.f));
            int idx = fi[j];
            int o0 = q * 5 + j;
            int o1 = Q5 + q * 5 + j;
            int o2 = 2 * Q5 + j * Q + q;
            if (o0 < out_size) out[o0] = dist;
            if (o1 < out_size) out[o1] = (float)idx;
            if (o2 < out_size) out[o2] = (float)labels[idx];
        }
    }
}

// ---------------- launch -----------------------------------------------------
extern "C" void kernel_launch(void* const* d_in, const int* in_sizes, int n_in,
                              void* d_out, int out_size)
{
    const float* X      = (const float*)d_in[0];
    const float* T      = (const float*)d_in[1];
    const int*   labels = (const int*)d_in[2];
    const int Q = in_sizes[0] / D_DIM;
    const int N = in_sizes[2];

    convert_norm<<<(Q * 32 + 255) / 256, 256>>>(X, Q, Q, 0);
    convert_norm<<<(NPAD * 32 + 255) / 256, 256>>>(T, N, NPAD, 1);

    dim3 grid((N + BN - 1) / BN, (Q + BM - 1) / BM);
    dist_gemm_mma<<<grid, 256>>>(N, Q);

    topk_rerank<<<Q, TKT>>>(X, T, labels, (float*)d_out, N, Q, out_size);
}

// round 12
// speedup vs baseline: 13.2391x; 1.0170x over previous
#include <cuda_runtime.h>
#include <cuda_bf16.h>
#include <cuda_fp16.h>
#include <cstdint>

#define D_DIM 512
#define QMAX  2048
#define NPAD  100096   // 782 * 128

// ---------------- scratch (device globals; no allocation allowed) -----------
// fp16 score = t2 - 2*dot + 2048  (guaranteed positive -> raw-bit sortable)
__device__ __align__(16) __half g_s[(size_t)QMAX * 100000];
__device__ float g_x2[QMAX];
__device__ float g_t2[NPAD];
__device__ __align__(256) __nv_bfloat16 g_xb[(size_t)QMAX * D_DIM];
__device__ __align__(256) __nv_bfloat16 g_tb[(size_t)NPAD * D_DIM];

#define SCORE_BIAS 2048.0f

// ---------------- helpers ----------------------------------------------------
__device__ __forceinline__ uint32_t smem_u32(const void* p) {
    uint32_t a;
    asm("{ .reg .u64 t; cvta.to.shared.u64 t, %1; cvt.u32.u64 %0, t; }" : "=r"(a) : "l"(p));
    return a;
}
__device__ __forceinline__ void cpasync16(uint32_t saddr, const void* g) {
    asm volatile("cp.async.cg.shared.global [%0], [%1], 16;"
                 :: "r"(saddr), "l"(__cvta_generic_to_global(g)) : "memory");
}
#define CP_COMMIT() asm volatile("cp.async.commit_group;" ::: "memory")
#define CP_WAIT0()  asm volatile("cp.async.wait_group 0;" ::: "memory")

// ---------------- kernel: fused fp32->bf16 convert + row norms --------------
__global__ void convert_norm(const float* __restrict__ src, int rows_valid,
                             int rows_total, int which)
{
    int gw   = (blockIdx.x * blockDim.x + threadIdx.x) >> 5;
    int lane = threadIdx.x & 31;
    if (gw >= rows_total) return;
    __nv_bfloat162* dst =
        reinterpret_cast<__nv_bfloat162*>(which ? g_tb : g_xb) + (size_t)gw * (D_DIM / 2);
    if (gw < rows_valid) {
        const float4* r4 = reinterpret_cast<const float4*>(src + (size_t)gw * D_DIM);
        float s = 0.f;
#pragma unroll
        for (int j = 0; j < 4; ++j) {
            float4 v = r4[lane + j * 32];
            s += v.x * v.x + v.y * v.y + v.z * v.z + v.w * v.w;
            dst[(lane + j * 32) * 2 + 0] = __floats2bfloat162_rn(v.x, v.y);
            dst[(lane + j * 32) * 2 + 1] = __floats2bfloat162_rn(v.z, v.w);
        }
#pragma unroll
        for (int o = 16; o; o >>= 1) s += __shfl_xor_sync(0xffffffffu, s, o);
        if (lane == 0) { if (which) g_t2[gw] = s; else g_x2[gw] = s; }
    } else {
        __nv_bfloat162 z = __floats2bfloat162_rn(0.f, 0.f);
#pragma unroll
        for (int j = 0; j < 4; ++j) {
            dst[(lane + j * 32) * 2 + 0] = z;
            dst[(lane + j * 32) * 2 + 1] = z;
        }
        if (lane == 0 && which) g_t2[gw] = 3.0e38f;
    }
}

// ---------------- mma.sync m16n8k16 bf16 wrapper (portable HMMA) -------------
__device__ __forceinline__ void mma16816(float* c, const uint32_t* a, const uint32_t* b) {
    asm volatile(
        "mma.sync.aligned.m16n8k16.row.col.f32.bf16.bf16.f32 "
        "{%0,%1,%2,%3}, {%4,%5,%6,%7}, {%8,%9}, {%0,%1,%2,%3};"
        : "+f"(c[0]), "+f"(c[1]), "+f"(c[2]), "+f"(c[3])
        : "r"(a[0]), "r"(a[1]), "r"(a[2]), "r"(a[3]), "r"(b[0]), "r"(b[1]));
}

// ---------------- kernel: bf16 HMMA distance GEMM, cp.async pipeline ---------
#define BM 128
#define BN 128
#define BK 32
#define SROW 80
#define ABYTES (BM * SROW)
#define BBYTES (BN * SROW)

__global__ __launch_bounds__(256, 2) void dist_gemm_mma(int N, int Q)
{
    __shared__ __align__(16) char smA[2][ABYTES];
    __shared__ __align__(16) char smB[2][BBYTES];

    const int tid = threadIdx.x;
    const int wid = tid >> 5;
    const int lane = tid & 31;
    const int tq = lane >> 2, tr = lane & 3;
    const int wm = wid & 3, wn = wid >> 2;
    const int bq = blockIdx.y * BM, bn = blockIdx.x * BN;

    const int lrow = tid >> 2;
    const int lseg = tid & 3;
    const int kseg = lseg * 8;
    const int ssm  = lrow * SROW + lseg * 16;
    int ar0 = bq + lrow;        if (ar0 > Q - 1) ar0 = Q - 1;
    int ar1 = bq + lrow + 64;   if (ar1 > Q - 1) ar1 = Q - 1;
    const size_t aoff0 = (size_t)ar0 * D_DIM;
    const size_t aoff1 = (size_t)ar1 * D_DIM;
    const size_t boff0 = (size_t)(bn + lrow) * D_DIM;
    const size_t boff1 = (size_t)(bn + lrow + 64) * D_DIM;

    const uint32_t sa[2] = { smem_u32(smA[0]) + ssm, smem_u32(smA[1]) + ssm };
    const uint32_t sb[2] = { smem_u32(smB[0]) + ssm, smem_u32(smB[1]) + ssm };

    float c[2][8][4];
#pragma unroll
    for (int mi = 0; mi < 2; ++mi)
#pragma unroll
        for (int ni = 0; ni < 8; ++ni)
#pragma unroll
            for (int j = 0; j < 4; ++j) c[mi][ni][j] = 0.f;

    cpasync16(sa[0],             g_xb + aoff0 + kseg);
    cpasync16(sa[0] + 64 * SROW, g_xb + aoff1 + kseg);
    cpasync16(sb[0],             g_tb + boff0 + kseg);
    cpasync16(sb[0] + 64 * SROW, g_tb + boff1 + kseg);
    CP_COMMIT();
    CP_WAIT0();
    __syncthreads();

#pragma unroll 2
    for (int kc = 0; kc < D_DIM / BK; ++kc) {
        const bool pre = (kc + 1) < (D_DIM / BK);
        if (pre) {
            const int ko = (kc + 1) * BK + kseg;
            const int nb = (kc + 1) & 1;
            cpasync16(sa[nb],             g_xb + aoff0 + ko);
            cpasync16(sa[nb] + 64 * SROW, g_xb + aoff1 + ko);
            cpasync16(sb[nb],             g_tb + boff0 + ko);
            cpasync16(sb[nb] + 64 * SROW, g_tb + boff1 + ko);
            CP_COMMIT();
        }
        const char* sA = smA[kc & 1];
        const char* sB = smB[kc & 1];
#pragma unroll
        for (int ks = 0; ks < 2; ++ks) {
            uint32_t a[2][4], b[8][2];
#pragma unroll
            for (int mi = 0; mi < 2; ++mi) {
                const char* p = sA + (wm * 32 + mi * 16 + tq) * SROW + ks * 32 + tr * 4;
                a[mi][0] = *reinterpret_cast<const uint32_t*>(p);
                a[mi][1] = *reinterpret_cast<const uint32_t*>(p + 8 * SROW);
                a[mi][2] = *reinterpret_cast<const uint32_t*>(p + 16);
                a[mi][3] = *reinterpret_cast<const uint32_t*>(p + 8 * SROW + 16);
            }
#pragma unroll
            for (int ni = 0; ni < 8; ++ni) {
                const char* p = sB + (wn * 64 + ni * 8 + tq) * SROW + ks * 32 + tr * 4;
                b[ni][0] = *reinterpret_cast<const uint32_t*>(p);
                b[ni][1] = *reinterpret_cast<const uint32_t*>(p + 16);
            }
#pragma unroll
            for (int mi = 0; mi < 2; ++mi)
#pragma unroll
                for (int ni = 0; ni < 8; ++ni)
                    mma16816(c[mi][ni], a[mi], b[ni]);
        }
        if (pre) {
            CP_WAIT0();
            __syncthreads();
        }
    }

    // epilogue: s = t2 - 2*dot + BIAS (positive fp16 -> raw bits sortable)
#pragma unroll
    for (int mi = 0; mi < 2; ++mi) {
#pragma unroll
        for (int h = 0; h < 2; ++h) {
            int q = bq + wm * 32 + mi * 16 + tq + h * 8;
            if (q >= Q) continue;
            __half* srow = g_s + (size_t)q * N;
#pragma unroll
            for (int ni = 0; ni < 8; ++ni) {
                int n0 = bn + wn * 64 + ni * 8 + tr * 2;
                if (n0 < N) {
                    float sx = g_t2[n0 + 0] - 2.f * c[mi][ni][h * 2 + 0] + SCORE_BIAS;
                    float sy = g_t2[n0 + 1] - 2.f * c[mi][ni][h * 2 + 1] + SCORE_BIAS;
                    *reinterpret_cast<__half2*>(srow + n0) = __floats2half2_rn(sx, sy);
                }
            }
        }
    }
}

// ---------------- topk: packed-key IMNMX top-3 scan -> 64 cand -> rerank -----
#define TKT 256

// top-3 maintenance on uint32 keys: pure min/max network (b0<=b1<=b2)
__device__ __forceinline__ void ins3u(uint32_t& b0, uint32_t& b1, uint32_t& b2, uint32_t k) {
    uint32_t t = min(b2, k);       // survivor of {b2, k}
    uint32_t u = min(b1, t);
    b2 = max(b1, t);
    b1 = max(b0, u);
    b0 = min(b0, u);
}

__device__ __forceinline__ void insert8u(uint32_t (&bk)[8], uint32_t k) {
#pragma unroll
    for (int j = 0; j < 8; ++j)
        if (k < bk[j]) { uint32_t t = bk[j]; bk[j] = k; k = t; }
}

__global__ __launch_bounds__(TKT) void topk_rerank(
    const float* __restrict__ X, const float* __restrict__ T,
    const int* __restrict__ labels, float* __restrict__ out,
    int N, int Q, int out_size)
{
    const int q = blockIdx.x;
    const int tid = threadIdx.x;
    const int lane = tid & 31, wid = tid >> 5;
    const __half* row = g_s + (size_t)q * N;

    // packed key: bits[12:28) = positive-fp16 score bits, bits[0:12) = local id
    // local id = (iter j << 3) | sub, decoded to n = ((j*TKT + tid) << 3) | sub
    uint32_t b0 = 0xFFFFFFFFu, b1 = 0xFFFFFFFFu, b2 = 0xFFFFFFFFu;

    const uint4* row8 = reinterpret_cast<const uint4*>(row);
    const int n8 = N >> 3;   // N % 8 == 0
    int j = 0;
    for (int i = tid; i < n8; i += TKT, ++j) {
        uint4 v = row8[i];
        uint32_t idb = (uint32_t)(j << 3);
        ins3u(b0, b1, b2, (((v.x << 12) & 0x0FFFF000u) | (idb | 0u)));
        ins3u(b0, b1, b2, (((v.x >>  4) & 0x0FFFF000u) | (idb | 1u)));
        ins3u(b0, b1, b2, (((v.y << 12) & 0x0FFFF000u) | (idb | 2u)));
        ins3u(b0, b1, b2, (((v.y >>  4) & 0x0FFFF000u) | (idb | 3u)));
        ins3u(b0, b1, b2, (((v.z << 12) & 0x0FFFF000u) | (idb | 4u)));
        ins3u(b0, b1, b2, (((v.z >>  4) & 0x0FFFF000u) | (idb | 5u)));
        ins3u(b0, b1, b2, (((v.w << 12) & 0x0FFFF000u) | (idb | 6u)));
        ins3u(b0, b1, b2, (((v.w >>  4) & 0x0FFFF000u) | (idb | 7u)));
    }

    // decode local ids to global indices; store (key, n) for merge
    __shared__ uint32_t sk[TKT * 3];
    __shared__ int      sn[TKT * 3];
    {
        uint32_t ks[3] = {b0, b1, b2};
#pragma unroll
        for (int t = 0; t < 3; ++t) {
            uint32_t id = ks[t] & 0xFFFu;
            int nn = ((((int)(id >> 3)) * TKT + tid) << 3) | (int)(id & 7u);
            sk[tid * 3 + t] = ks[t];
            sn[tid * 3 + t] = (ks[t] == 0xFFFFFFFFu) ? 0x7fffffff : nn;
        }
    }
    __syncthreads();

    // stage 1: lane0 of each warp merges its warp's 96 keys -> warp top-8
    __shared__ int wiv[64];
    if (lane == 0) {
        uint32_t mk[8];
#pragma unroll
        for (int t = 0; t < 8; ++t) mk[t] = 0xFFFFFFFFu;
        uint32_t mthr = 0xFFFFFFFFu;
        const int base = wid * 96;
        int src[8];
#pragma unroll
        for (int t = 0; t < 8; ++t) src[t] = -1;
        for (int t = 0; t < 96; ++t) {
            uint32_t k = sk[base + t];
            if (k < mthr) { insert8u(mk, k); mthr = mk[7]; }
        }
        // second pass to recover indices of the 8 winners (96 reads, cheap)
        int cnt = 0;
        for (int t = 0; t < 96 && cnt < 8; ++t) {
            uint32_t k = sk[base + t];
#pragma unroll
            for (int w = 0; w < 8; ++w)
                if (k == mk[w] && src[w] < 0) { src[w] = sn[base + t]; ++cnt; break; }
        }
#pragma unroll
        for (int t = 0; t < 8; ++t) wiv[wid * 8 + t] = (src[t] < 0) ? 0x7fffffff : src[t];
    }
    __syncthreads();

    // exact fp32 rerank of the 64 candidates (warp wid -> candidates wid*8..+7)
    __shared__ float ed[64];
    {
        const float4* x4 = reinterpret_cast<const float4*>(X + (size_t)q * D_DIM);
        float4 xv[4];
#pragma unroll
        for (int jj = 0; jj < 4; ++jj) xv[jj] = x4[lane + jj * 32];
        for (int cc = 0; cc < 8; ++cc) {
            int idx = wiv[wid * 8 + cc];
            float d2 = 3.4e38f;
            if (idx >= 0 && idx < N) {
                const float4* t4 = reinterpret_cast<const float4*>(T + (size_t)idx * D_DIM);
                float dot = 0.f;
#pragma unroll
                for (int jj = 0; jj < 4; ++jj) {
                    float4 tv = t4[lane + jj * 32];
                    dot += xv[jj].x * tv.x + xv[jj].y * tv.y + xv[jj].z * tv.z + xv[jj].w * tv.w;
                }
#pragma unroll
                for (int o = 16; o; o >>= 1) dot += __shfl_xor_sync(0xffffffffu, dot, o);
                d2 = g_x2[q] + g_t2[idx] - 2.f * dot;
            }
            if (lane == 0) ed[wid * 8 + cc] = d2;
        }
    }
    __syncthreads();

    // final exact top-5 with (d2, idx) tie-break; write all three output segments
    if (tid == 0) {
        float fd[5]; int fi[5];
#pragma unroll
        for (int t = 0; t < 5; ++t) { fd[t] = 3.4e38f; fi[t] = 0x7fffffff; }
        for (int t = 0; t < 64; ++t) {
            float vd = ed[t]; int vi = wiv[t];
#pragma unroll
            for (int jj = 0; jj < 5; ++jj) {
                bool lt = (vd < fd[jj]) || (vd == fd[jj] && vi < fi[jj]);
                if (lt) { float td = fd[jj]; int ti = fi[jj];
                          fd[jj] = vd; fi[jj] = vi; vd = td; vi = ti; }
            }
        }
        const int Q5 = Q * 5;
#pragma unroll
        for (int jj = 0; jj < 5; ++jj) {
            float dist = sqrtf(fmaxf(fd[jj], 0.f));
            int idx = fi[jj];
            int o0 = q * 5 + jj;
            int o1 = Q5 + q * 5 + jj;
            int o2 = 2 * Q5 + jj * Q + q;
            if (o0 < out_size) out[o0] = dist;
            if (o1 < out_size) out[o1] = (float)idx;
            if (o2 < out_size) out[o2] = (float)labels[idx];
        }
    }
}

// ---------------- launch -----------------------------------------------------
extern "C" void kernel_launch(void* const* d_in, const int* in_sizes, int n_in,
                              void* d_out, int out_size)
{
    const float* X      = (const float*)d_in[0];
    const float* T      = (const float*)d_in[1];
    const int*   labels = (const int*)d_in[2];
    const int Q = in_sizes[0] / D_DIM;
    const int N = in_sizes[2];

    convert_norm<<<(Q * 32 + 255) / 256, 256>>>(X, Q, Q, 0);
    convert_norm<<<(NPAD * 32 + 255) / 256, 256>>>(T, N, NPAD, 1);

    dim3 grid((N + BN - 1) / BN, (Q + BM - 1) / BM);
    dist_gemm_mma<<<grid, 256>>>(N, Q);

    topk_rerank<<<Q, TKT>>>(X, T, labels, (float*)d_out, N, Q, out_size);
}

// round 15
// speedup vs baseline: 15.9233x; 1.2027x over previous
#include <cuda_runtime.h>
#include <cuda_bf16.h>
#include <cuda_fp16.h>
#include <cstdint>

#define D_DIM 512
#define QMAX  2048
#define NPAD  100096   // 782 * 128
#define MAXCAND 4740   // >= ceil(N/128)*6

// ---------------- scratch (device globals; no allocation allowed) -----------
__device__ float g_x2[QMAX];
__device__ float g_t2[NPAD];
__device__ __align__(256) __nv_bfloat16 g_xb[(size_t)QMAX * D_DIM];
__device__ __align__(256) __nv_bfloat16 g_tb[(size_t)NPAD * D_DIM];
// per-(query, 64-col tile) top-3 candidates: u64 = (fp16 score bits << 32) | n
__device__ __align__(16) unsigned long long g_cand[(size_t)QMAX * MAXCAND];

#define SCORE_BIAS 2048.0f

// ---------------- helpers ----------------------------------------------------
__device__ __forceinline__ uint32_t smem_u32(const void* p) {
    uint32_t a;
    asm("{ .reg .u64 t; cvta.to.shared.u64 t, %1; cvt.u32.u64 %0, t; }" : "=r"(a) : "l"(p));
    return a;
}
__device__ __forceinline__ void cpasync16(uint32_t saddr, const void* g) {
    asm volatile("cp.async.cg.shared.global [%0], [%1], 16;"
                 :: "r"(saddr), "l"(__cvta_generic_to_global(g)) : "memory");
}
#define CP_COMMIT() asm volatile("cp.async.commit_group;" ::: "memory")
#define CP_WAIT0()  asm volatile("cp.async.wait_group 0;" ::: "memory")

// top-3 maintenance on u32 keys (b0<=b1<=b2), pure min/max network
__device__ __forceinline__ void ins3u(uint32_t& b0, uint32_t& b1, uint32_t& b2, uint32_t k) {
    uint32_t t = min(b2, k);
    uint32_t u = min(b1, t);
    b2 = max(b1, t);
    b1 = max(b0, u);
    b0 = min(b0, u);
}
// top-3 on u64 keys
__device__ __forceinline__ void ins3u64(unsigned long long& b0, unsigned long long& b1,
                                        unsigned long long& b2, unsigned long long k) {
    unsigned long long t = k  < b2 ? k  : b2;
    unsigned long long u = t  < b1 ? t  : b1;
    b2 = b1 > t ? b1 : t;
    b1 = b0 > u ? b0 : u;
    b0 = b0 < u ? b0 : u;
}
__device__ __forceinline__ void insert8u64(unsigned long long (&bk)[8], unsigned long long k) {
#pragma unroll
    for (int j = 0; j < 8; ++j)
        if (k < bk[j]) { unsigned long long t = bk[j]; bk[j] = k; k = t; }
}

// ---------------- kernel: fused fp32->bf16 convert + row norms --------------
__global__ void convert_norm(const float* __restrict__ src, int rows_valid,
                             int rows_total, int which)
{
    int gw   = (blockIdx.x * blockDim.x + threadIdx.x) >> 5;
    int lane = threadIdx.x & 31;
    if (gw >= rows_total) return;
    __nv_bfloat162* dst =
        reinterpret_cast<__nv_bfloat162*>(which ? g_tb : g_xb) + (size_t)gw * (D_DIM / 2);
    if (gw < rows_valid) {
        const float4* r4 = reinterpret_cast<const float4*>(src + (size_t)gw * D_DIM);
        float s = 0.f;
#pragma unroll
        for (int j = 0; j < 4; ++j) {
            float4 v = r4[lane + j * 32];
            s += v.x * v.x + v.y * v.y + v.z * v.z + v.w * v.w;
            dst[(lane + j * 32) * 2 + 0] = __floats2bfloat162_rn(v.x, v.y);
            dst[(lane + j * 32) * 2 + 1] = __floats2bfloat162_rn(v.z, v.w);
        }
#pragma unroll
        for (int o = 16; o; o >>= 1) s += __shfl_xor_sync(0xffffffffu, s, o);
        if (lane == 0) { if (which) g_t2[gw] = s; else g_x2[gw] = s; }
    } else {
        __nv_bfloat162 z = __floats2bfloat162_rn(0.f, 0.f);
#pragma unroll
        for (int j = 0; j < 4; ++j) {
            dst[(lane + j * 32) * 2 + 0] = z;
            dst[(lane + j * 32) * 2 + 1] = z;
        }
        if (lane == 0 && which) g_t2[gw] = 3.0e38f;
    }
}

// ---------------- mma.sync m16n8k16 bf16 wrapper (portable HMMA) -------------
__device__ __forceinline__ void mma16816(float* c, const uint32_t* a, const uint32_t* b) {
    asm volatile(
        "mma.sync.aligned.m16n8k16.row.col.f32.bf16.bf16.f32 "
        "{%0,%1,%2,%3}, {%4,%5,%6,%7}, {%8,%9}, {%0,%1,%2,%3};"
        : "+f"(c[0]), "+f"(c[1]), "+f"(c[2]), "+f"(c[3])
        : "r"(a[0]), "r"(a[1]), "r"(a[2]), "r"(a[3]), "r"(b[0]), "r"(b[1]));
}

// ---------------- kernel: bf16 HMMA GEMM + fused candidate selection ---------
#define BM 128
#define BN 128
#define BK 32
#define SROW 80
#define ABYTES (BM * SROW)
#define BBYTES (BN * SROW)

__global__ __launch_bounds__(256, 2) void dist_gemm_mma(int N, int Q, int cstride)
{
    __shared__ __align__(16) char smA[2][ABYTES];
    __shared__ __align__(16) char smB[2][BBYTES];

    const int tid = threadIdx.x;
    const int wid = tid >> 5;
    const int lane = tid & 31;
    const int tq = lane >> 2, tr = lane & 3;
    const int wm = wid & 3, wn = wid >> 2;
    const int bq = blockIdx.y * BM, bn = blockIdx.x * BN;

    const int lrow = tid >> 2;
    const int lseg = tid & 3;
    const int kseg = lseg * 8;
    const int ssm  = lrow * SROW + lseg * 16;
    int ar0 = bq + lrow;        if (ar0 > Q - 1) ar0 = Q - 1;
    int ar1 = bq + lrow + 64;   if (ar1 > Q - 1) ar1 = Q - 1;
    const size_t aoff0 = (size_t)ar0 * D_DIM;
    const size_t aoff1 = (size_t)ar1 * D_DIM;
    const size_t boff0 = (size_t)(bn + lrow) * D_DIM;
    const size_t boff1 = (size_t)(bn + lrow + 64) * D_DIM;

    const uint32_t sa[2] = { smem_u32(smA[0]) + ssm, smem_u32(smA[1]) + ssm };
    const uint32_t sb[2] = { smem_u32(smB[0]) + ssm, smem_u32(smB[1]) + ssm };

    float c[2][8][4];
#pragma unroll
    for (int mi = 0; mi < 2; ++mi)
#pragma unroll
        for (int ni = 0; ni < 8; ++ni)
#pragma unroll
            for (int j = 0; j < 4; ++j) c[mi][ni][j] = 0.f;

    cpasync16(sa[0],             g_xb + aoff0 + kseg);
    cpasync16(sa[0] + 64 * SROW, g_xb + aoff1 + kseg);
    cpasync16(sb[0],             g_tb + boff0 + kseg);
    cpasync16(sb[0] + 64 * SROW, g_tb + boff1 + kseg);
    CP_COMMIT();
    CP_WAIT0();
    __syncthreads();

#pragma unroll 2
    for (int kc = 0; kc < D_DIM / BK; ++kc) {
        const bool pre = (kc + 1) < (D_DIM / BK);
        if (pre) {
            const int ko = (kc + 1) * BK + kseg;
            const int nb = (kc + 1) & 1;
            cpasync16(sa[nb],             g_xb + aoff0 + ko);
            cpasync16(sa[nb] + 64 * SROW, g_xb + aoff1 + ko);
            cpasync16(sb[nb],             g_tb + boff0 + ko);
            cpasync16(sb[nb] + 64 * SROW, g_tb + boff1 + ko);
            CP_COMMIT();
        }
        const char* sA = smA[kc & 1];
        const char* sB = smB[kc & 1];
#pragma unroll
        for (int ks = 0; ks < 2; ++ks) {
            uint32_t a[2][4], b[8][2];
#pragma unroll
            for (int mi = 0; mi < 2; ++mi) {
                const char* p = sA + (wm * 32 + mi * 16 + tq) * SROW + ks * 32 + tr * 4;
                a[mi][0] = *reinterpret_cast<const uint32_t*>(p);
                a[mi][1] = *reinterpret_cast<const uint32_t*>(p + 8 * SROW);
                a[mi][2] = *reinterpret_cast<const uint32_t*>(p + 16);
                a[mi][3] = *reinterpret_cast<const uint32_t*>(p + 8 * SROW + 16);
            }
#pragma unroll
            for (int ni = 0; ni < 8; ++ni) {
                const char* p = sB + (wn * 64 + ni * 8 + tq) * SROW + ks * 32 + tr * 4;
                b[ni][0] = *reinterpret_cast<const uint32_t*>(p);
                b[ni][1] = *reinterpret_cast<const uint32_t*>(p + 16);
            }
#pragma unroll
            for (int mi = 0; mi < 2; ++mi)
#pragma unroll
                for (int ni = 0; ni < 8; ++ni)
                    mma16816(c[mi][ni], a[mi], b[ni]);
        }
        if (pre) {
            CP_WAIT0();
            __syncthreads();
        }
    }

    // ---- fused epilogue: per-(query, 64-col warp tile) top-3 candidates ----
    // scores for n >= N are +inf (padded g_tb rows are zero, g_t2 sentinel 3e38)
    float t2v[16];
#pragma unroll
    for (int ni = 0; ni < 8; ++ni) {
        t2v[ni * 2 + 0] = g_t2[bn + wn * 64 + ni * 8 + tr * 2 + 0] + SCORE_BIAS;
        t2v[ni * 2 + 1] = g_t2[bn + wn * 64 + ni * 8 + tr * 2 + 1] + SCORE_BIAS;
    }

#pragma unroll
    for (int mi = 0; mi < 2; ++mi) {
#pragma unroll
        for (int h = 0; h < 2; ++h) {
            const int q = bq + wm * 32 + mi * 16 + tq + h * 8;
            // per-thread top-2 over 16 values; key = (fp16bits<<16) | local_col
            uint32_t k0 = 0xFFFFFFFFu, k1 = 0xFFFFFFFFu;
#pragma unroll
            for (int ni = 0; ni < 8; ++ni) {
#pragma unroll
                for (int sub = 0; sub < 2; ++sub) {
                    float s = t2v[ni * 2 + sub] - 2.f * c[mi][ni][h * 2 + sub];
                    uint32_t hb = (uint32_t)__half_as_ushort(__float2half_rn(s));
                    uint32_t key = (hb << 16) | (uint32_t)(ni * 8 + tr * 2 + sub);
                    uint32_t t = min(k1, key);
                    k1 = max(k0, t);
                    k0 = min(k0, t);
                }
            }
            // merge across the 4 tr lanes (same query) -> tile top-3
            uint32_t b0 = k0, b1 = k1, b2 = 0xFFFFFFFFu;
            {
                uint32_t r0 = __shfl_xor_sync(0xffffffffu, b0, 1);
                uint32_t r1 = __shfl_xor_sync(0xffffffffu, b1, 1);
                ins3u(b0, b1, b2, r0);
                ins3u(b0, b1, b2, r1);
            }
            {
                uint32_t r0 = __shfl_xor_sync(0xffffffffu, b0, 2);
                uint32_t r1 = __shfl_xor_sync(0xffffffffu, b1, 2);
                uint32_t r2 = __shfl_xor_sync(0xffffffffu, b2, 2);
                ins3u(b0, b1, b2, r0);
                ins3u(b0, b1, b2, r1);
                ins3u(b0, b1, b2, r2);
            }
            if (tr == 0 && q < Q) {
                const int ncol = bn + wn * 64;
                unsigned long long* dst =
                    g_cand + (size_t)q * cstride + ((size_t)blockIdx.x * 2 + wn) * 3;
                dst[0] = ((unsigned long long)(b0 >> 16) << 32) | (uint32_t)(ncol + (b0 & 63u));
                dst[1] = ((unsigned long long)(b1 >> 16) << 32) | (uint32_t)(ncol + (b1 & 63u));
                dst[2] = ((unsigned long long)(b2 >> 16) << 32) | (uint32_t)(ncol + (b2 & 63u));
            }
        }
    }
}

// ---------------- final: merge candidates -> top-64 -> exact rerank ----------
#define TKT 256

__global__ __launch_bounds__(TKT) void topk_rerank(
    const float* __restrict__ X, const float* __restrict__ T,
    const int* __restrict__ labels, float* __restrict__ out,
    int N, int Q, int out_size, int ncand)
{
    const int q = blockIdx.x;
    const int tid = threadIdx.x;
    const int lane = tid & 31, wid = tid >> 5;
    const unsigned long long* crow = g_cand + (size_t)q * ncand;

    unsigned long long b0 = ~0ull, b1 = ~0ull, b2 = ~0ull;
    for (int i = tid; i < ncand; i += TKT)
        ins3u64(b0, b1, b2, crow[i]);

    __shared__ unsigned long long sk[TKT * 3];
    sk[tid * 3 + 0] = b0;
    sk[tid * 3 + 1] = b1;
    sk[tid * 3 + 2] = b2;
    __syncthreads();

    // stage 1: lane0 of each warp merges its warp's 96 keys -> warp top-8
    __shared__ int wiv[64];
    if (lane == 0) {
        unsigned long long mk[8];
#pragma unroll
        for (int t = 0; t < 8; ++t) mk[t] = ~0ull;
        unsigned long long mthr = ~0ull;
        const int base = wid * 96;
        for (int t = 0; t < 96; ++t) {
            unsigned long long k = sk[base + t];
            if (k < mthr) { insert8u64(mk, k); mthr = mk[7]; }
        }
#pragma unroll
        for (int t = 0; t < 8; ++t)
            wiv[wid * 8 + t] = (int)(uint32_t)(mk[t] & 0xFFFFFFFFull);
    }
    __syncthreads();

    // exact fp32 rerank of the 64 candidates (warp wid -> candidates wid*8..+7)
    __shared__ float ed[64];
    {
        const float4* x4 = reinterpret_cast<const float4*>(X + (size_t)q * D_DIM);
        float4 xv[4];
#pragma unroll
        for (int jj = 0; jj < 4; ++jj) xv[jj] = x4[lane + jj * 32];
        for (int cc = 0; cc < 8; ++cc) {
            int idx = wiv[wid * 8 + cc];
            float d2 = 3.4e38f;
            if (idx >= 0 && idx < N) {
                const float4* t4 = reinterpret_cast<const float4*>(T + (size_t)idx * D_DIM);
                float dot = 0.f;
#pragma unroll
                for (int jj = 0; jj < 4; ++jj) {
                    float4 tv = t4[lane + jj * 32];
                    dot += xv[jj].x * tv.x + xv[jj].y * tv.y + xv[jj].z * tv.z + xv[jj].w * tv.w;
                }
#pragma unroll
                for (int o = 16; o; o >>= 1) dot += __shfl_xor_sync(0xffffffffu, dot, o);
                d2 = g_x2[q] + g_t2[idx] - 2.f * dot;
            }
            if (lane == 0) ed[wid * 8 + cc] = d2;
        }
    }
    __syncthreads();

    // final exact top-5 with (d2, idx) tie-break; write all three output segments
    if (tid == 0) {
        float fd[5]; int fi[5];
#pragma unroll
        for (int t = 0; t < 5; ++t) { fd[t] = 3.4e38f; fi[t] = 0x7fffffff; }
        for (int t = 0; t < 64; ++t) {
            float vd = ed[t]; int vi = wiv[t];
#pragma unroll
            for (int jj = 0; jj < 5; ++jj) {
                bool lt = (vd < fd[jj]) || (vd == fd[jj] && vi < fi[jj]);
                if (lt) { float td = fd[jj]; int ti = fi[jj];
                          fd[jj] = vd; fi[jj] = vi; vd = td; vi = ti; }
            }
        }
        const int Q5 = Q * 5;
#pragma unroll
        for (int jj = 0; jj < 5; ++jj) {
            float dist = sqrtf(fmaxf(fd[jj], 0.f));
            int idx = fi[jj];
            int o0 = q * 5 + jj;
            int o1 = Q5 + q * 5 + jj;
            int o2 = 2 * Q5 + jj * Q + q;
            if (o0 < out_size) out[o0] = dist;
            if (o1 < out_size) out[o1] = (float)idx;
            if (o2 < out_size) out[o2] = (float)labels[idx];
        }
    }
}

// ---------------- launch -----------------------------------------------------
extern "C" void kernel_launch(void* const* d_in, const int* in_sizes, int n_in,
                              void* d_out, int out_size)
{
    const float* X      = (const float*)d_in[0];
    const float* T      = (const float*)d_in[1];
    const int*   labels = (const int*)d_in[2];
    const int Q = in_sizes[0] / D_DIM;
    const int N = in_sizes[2];

    convert_norm<<<(Q * 32 + 255) / 256, 256>>>(X, Q, Q, 0);
    convert_norm<<<(NPAD * 32 + 255) / 256, 256>>>(T, N, NPAD, 1);

    const int ntiles = (N + BN - 1) / BN;
    const int cstride = ntiles * 6;   // 2 warp-tiles per CTA tile, 3 entries each

    dim3 grid(ntiles, (Q + BM - 1) / BM);
    dist_gemm_mma<<<grid, 256>>>(N, Q, cstride);

    topk_rerank<<<Q, TKT>>>(X, T, labels, (float*)d_out, N, Q, out_size, cstride);
}

// round 16
// speedup vs baseline: 16.8831x; 1.0603x over previous
#include <cuda_runtime.h>
#include <cuda_bf16.h>
#include <cuda_fp16.h>
#include <cuda_fp8.h>
#include <cstdint>

#define D_DIM 512
#define QMAX  2048
#define NPAD  100096   // 782 * 128
#define MAXCAND 4740   // >= ceil(N/128)*6

// ---------------- scratch (device globals; no allocation allowed) -----------
__device__ float g_x2[QMAX];
__device__ float g_t2[NPAD];
__device__ __align__(256) uint8_t g_xb[(size_t)QMAX * D_DIM];   // e4m3
__device__ __align__(256) uint8_t g_tb[(size_t)NPAD * D_DIM];   // e4m3
// per-(query, 64-col tile) top-3 candidates: u64 = (fp16 score bits << 32) | n
__device__ __align__(16) unsigned long long g_cand[(size_t)QMAX * MAXCAND];

#define SCORE_BIAS 2048.0f

// ---------------- helpers ----------------------------------------------------
__device__ __forceinline__ uint32_t smem_u32(const void* p) {
    uint32_t a;
    asm("{ .reg .u64 t; cvta.to.shared.u64 t, %1; cvt.u32.u64 %0, t; }" : "=r"(a) : "l"(p));
    return a;
}
__device__ __forceinline__ void cpasync16(uint32_t saddr, const void* g) {
    asm volatile("cp.async.cg.shared.global [%0], [%1], 16;"
                 :: "r"(saddr), "l"(__cvta_generic_to_global(g)) : "memory");
}
#define CP_COMMIT() asm volatile("cp.async.commit_group;" ::: "memory")
#define CP_WAIT0()  asm volatile("cp.async.wait_group 0;" ::: "memory")

__device__ __forceinline__ void ins3u(uint32_t& b0, uint32_t& b1, uint32_t& b2, uint32_t k) {
    uint32_t t = min(b2, k);
    uint32_t u = min(b1, t);
    b2 = max(b1, t);
    b1 = max(b0, u);
    b0 = min(b0, u);
}
__device__ __forceinline__ void ins3u64(unsigned long long& b0, unsigned long long& b1,
                                        unsigned long long& b2, unsigned long long k) {
    unsigned long long t = k  < b2 ? k  : b2;
    unsigned long long u = t  < b1 ? t  : b1;
    b2 = b1 > t ? b1 : t;
    b1 = b0 > u ? b0 : u;
    b0 = b0 < u ? b0 : u;
}
__device__ __forceinline__ void insert8u64(unsigned long long (&bk)[8], unsigned long long k) {
#pragma unroll
    for (int j = 0; j < 8; ++j)
        if (k < bk[j]) { unsigned long long t = bk[j]; bk[j] = k; k = t; }
}

// ---------------- kernel: fused fp32->e4m3 convert + row norms ---------------
__global__ void convert_norm(const float* __restrict__ src, int rows_valid,
                             int rows_total, int which)
{
    int gw   = (blockIdx.x * blockDim.x + threadIdx.x) >> 5;
    int lane = threadIdx.x & 31;
    if (gw >= rows_total) return;
    uchar4* dst = reinterpret_cast<uchar4*>((which ? g_tb : g_xb) + (size_t)gw * D_DIM);
    if (gw < rows_valid) {
        const float4* r4 = reinterpret_cast<const float4*>(src + (size_t)gw * D_DIM);
        float s = 0.f;
#pragma unroll
        for (int j = 0; j < 4; ++j) {
            float4 v = r4[lane + j * 32];
            s += v.x * v.x + v.y * v.y + v.z * v.z + v.w * v.w;
            uchar4 o;
            o.x = __nv_fp8_e4m3(v.x).__x;
            o.y = __nv_fp8_e4m3(v.y).__x;
            o.z = __nv_fp8_e4m3(v.z).__x;
            o.w = __nv_fp8_e4m3(v.w).__x;
            dst[lane + j * 32] = o;
        }
#pragma unroll
        for (int o = 16; o; o >>= 1) s += __shfl_xor_sync(0xffffffffu, s, o);
        if (lane == 0) { if (which) g_t2[gw] = s; else g_x2[gw] = s; }
    } else {
        uchar4 z = make_uchar4(0, 0, 0, 0);
#pragma unroll
        for (int j = 0; j < 4; ++j) dst[lane + j * 32] = z;
        if (lane == 0 && which) g_t2[gw] = 3.0e38f;
    }
}

// ---------------- mma.sync m16n8k32 e4m3 wrapper (portable, sm_89+) ----------
__device__ __forceinline__ void mma16832(float* c, const uint32_t* a, const uint32_t* b) {
    asm volatile(
        "mma.sync.aligned.m16n8k32.row.col.f32.e4m3.e4m3.f32 "
        "{%0,%1,%2,%3}, {%4,%5,%6,%7}, {%8,%9}, {%0,%1,%2,%3};"
        : "+f"(c[0]), "+f"(c[1]), "+f"(c[2]), "+f"(c[3])
        : "r"(a[0]), "r"(a[1]), "r"(a[2]), "r"(a[3]), "r"(b[0]), "r"(b[1]));
}

// ---------------- kernel: e4m3 HMMA GEMM + fused candidate selection ---------
// chunk = 64 fp8 elems = 64 bytes/row: byte layout identical to bf16 BK=32.
#define BM 128
#define BN 128
#define BKB 64                  // bytes (= fp8 elems) per chunk
#define NCHUNK (D_DIM / BKB)    // 8
#define SROW 80
#define ABYTES (BM * SROW)
#define BBYTES (BN * SROW)

__global__ __launch_bounds__(256, 2) void dist_gemm_mma(int N, int Q, int cstride)
{
    __shared__ __align__(16) char smA[2][ABYTES];
    __shared__ __align__(16) char smB[2][BBYTES];

    const int tid = threadIdx.x;
    const int wid = tid >> 5;
    const int lane = tid & 31;
    const int tq = lane >> 2, tr = lane & 3;
    const int wm = wid & 3, wn = wid >> 2;
    const int bq = blockIdx.y * BM, bn = blockIdx.x * BN;

    const int lrow = tid >> 2;
    const int lseg = tid & 3;
    const int kseg = lseg * 16;                // byte offset within chunk
    const int ssm  = lrow * SROW + lseg * 16;
    int ar0 = bq + lrow;        if (ar0 > Q - 1) ar0 = Q - 1;
    int ar1 = bq + lrow + 64;   if (ar1 > Q - 1) ar1 = Q - 1;
    const size_t aoff0 = (size_t)ar0 * D_DIM;  // bytes (1 B/elem)
    const size_t aoff1 = (size_t)ar1 * D_DIM;
    const size_t boff0 = (size_t)(bn + lrow) * D_DIM;
    const size_t boff1 = (size_t)(bn + lrow + 64) * D_DIM;

    const uint32_t sa[2] = { smem_u32(smA[0]) + ssm, smem_u32(smA[1]) + ssm };
    const uint32_t sb[2] = { smem_u32(smB[0]) + ssm, smem_u32(smB[1]) + ssm };

    float c[2][8][4];
#pragma unroll
    for (int mi = 0; mi < 2; ++mi)
#pragma unroll
        for (int ni = 0; ni < 8; ++ni)
#pragma unroll
            for (int j = 0; j < 4; ++j) c[mi][ni][j] = 0.f;

    cpasync16(sa[0],             g_xb + aoff0 + kseg);
    cpasync16(sa[0] + 64 * SROW, g_xb + aoff1 + kseg);
    cpasync16(sb[0],             g_tb + boff0 + kseg);
    cpasync16(sb[0] + 64 * SROW, g_tb + boff1 + kseg);
    CP_COMMIT();
    CP_WAIT0();
    __syncthreads();

#pragma unroll 2
    for (int kc = 0; kc < NCHUNK; ++kc) {
        const bool pre = (kc + 1) < NCHUNK;
        if (pre) {
            const int ko = (kc + 1) * BKB + kseg;
            const int nb = (kc + 1) & 1;
            cpasync16(sa[nb],             g_xb + aoff0 + ko);
            cpasync16(sa[nb] + 64 * SROW, g_xb + aoff1 + ko);
            cpasync16(sb[nb],             g_tb + boff0 + ko);
            cpasync16(sb[nb] + 64 * SROW, g_tb + boff1 + ko);
            CP_COMMIT();
        }
        const char* sA = smA[kc & 1];
        const char* sB = smB[kc & 1];
#pragma unroll
        for (int ks = 0; ks < 2; ++ks) {       // ks covers 32 fp8 = 32 bytes
            uint32_t a[2][4], b[8][2];
#pragma unroll
            for (int mi = 0; mi < 2; ++mi) {
                const char* p = sA + (wm * 32 + mi * 16 + tq) * SROW + ks * 32 + tr * 4;
                a[mi][0] = *reinterpret_cast<const uint32_t*>(p);
                a[mi][1] = *reinterpret_cast<const uint32_t*>(p + 8 * SROW);
                a[mi][2] = *reinterpret_cast<const uint32_t*>(p + 16);
                a[mi][3] = *reinterpret_cast<const uint32_t*>(p + 8 * SROW + 16);
            }
#pragma unroll
            for (int ni = 0; ni < 8; ++ni) {
                const char* p = sB + (wn * 64 + ni * 8 + tq) * SROW + ks * 32 + tr * 4;
                b[ni][0] = *reinterpret_cast<const uint32_t*>(p);
                b[ni][1] = *reinterpret_cast<const uint32_t*>(p + 16);
            }
#pragma unroll
            for (int mi = 0; mi < 2; ++mi)
#pragma unroll
                for (int ni = 0; ni < 8; ++ni)
                    mma16832(c[mi][ni], a[mi], b[ni]);
        }
        if (pre) {
            CP_WAIT0();
            __syncthreads();
        }
    }

    // ---- fused epilogue: per-(query, 64-col warp tile) top-3 candidates ----
    float t2v[16];
#pragma unroll
    for (int ni = 0; ni < 8; ++ni) {
        t2v[ni * 2 + 0] = g_t2[bn + wn * 64 + ni * 8 + tr * 2 + 0] + SCORE_BIAS;
        t2v[ni * 2 + 1] = g_t2[bn + wn * 64 + ni * 8 + tr * 2 + 1] + SCORE_BIAS;
    }

#pragma unroll
    for (int mi = 0; mi < 2; ++mi) {
#pragma unroll
        for (int h = 0; h < 2; ++h) {
            const int q = bq + wm * 32 + mi * 16 + tq + h * 8;
            uint32_t k0 = 0xFFFFFFFFu, k1 = 0xFFFFFFFFu;
#pragma unroll
            for (int ni = 0; ni < 8; ++ni) {
#pragma unroll
                for (int sub = 0; sub < 2; ++sub) {
                    float s = t2v[ni * 2 + sub] - 2.f * c[mi][ni][h * 2 + sub];
                    uint32_t hb = (uint32_t)__half_as_ushort(__float2half_rn(s));
                    uint32_t key = (hb << 16) | (uint32_t)(ni * 8 + tr * 2 + sub);
                    uint32_t t = min(k1, key);
                    k1 = max(k0, t);
                    k0 = min(k0, t);
                }
            }
            uint32_t b0 = k0, b1 = k1, b2 = 0xFFFFFFFFu;
            {
                uint32_t r0 = __shfl_xor_sync(0xffffffffu, b0, 1);
                uint32_t r1 = __shfl_xor_sync(0xffffffffu, b1, 1);
                ins3u(b0, b1, b2, r0);
                ins3u(b0, b1, b2, r1);
            }
            {
                uint32_t r0 = __shfl_xor_sync(0xffffffffu, b0, 2);
                uint32_t r1 = __shfl_xor_sync(0xffffffffu, b1, 2);
                uint32_t r2 = __shfl_xor_sync(0xffffffffu, b2, 2);
                ins3u(b0, b1, b2, r0);
                ins3u(b0, b1, b2, r1);
                ins3u(b0, b1, b2, r2);
            }
            if (tr == 0 && q < Q) {
                const int ncol = bn + wn * 64;
                unsigned long long* dst =
                    g_cand + (size_t)q * cstride + ((size_t)blockIdx.x * 2 + wn) * 3;
                dst[0] = ((unsigned long long)(b0 >> 16) << 32) | (uint32_t)(ncol + (b0 & 63u));
                dst[1] = ((unsigned long long)(b1 >> 16) << 32) | (uint32_t)(ncol + (b1 & 63u));
                dst[2] = ((unsigned long long)(b2 >> 16) << 32) | (uint32_t)(ncol + (b2 & 63u));
            }
        }
    }
}

// ---------------- final: merge candidates -> top-64 -> exact rerank ----------
#define TKT 256

__global__ __launch_bounds__(TKT) void topk_rerank(
    const float* __restrict__ X, const float* __restrict__ T,
    const int* __restrict__ labels, float* __restrict__ out,
    int N, int Q, int out_size, int ncand)
{
    const int q = blockIdx.x;
    const int tid = threadIdx.x;
    const int lane = tid & 31, wid = tid >> 5;
    const unsigned long long* crow = g_cand + (size_t)q * ncand;

    unsigned long long b0 = ~0ull, b1 = ~0ull, b2 = ~0ull;
    for (int i = tid; i < ncand; i += TKT)
        ins3u64(b0, b1, b2, crow[i]);

    __shared__ unsigned long long sk[TKT * 3];
    sk[tid * 3 + 0] = b0;
    sk[tid * 3 + 1] = b1;
    sk[tid * 3 + 2] = b2;
    __syncthreads();

    __shared__ int wiv[64];
    if (lane == 0) {
        unsigned long long mk[8];
#pragma unroll
        for (int t = 0; t < 8; ++t) mk[t] = ~0ull;
        unsigned long long mthr = ~0ull;
        const int base = wid * 96;
        for (int t = 0; t < 96; ++t) {
            unsigned long long k = sk[base + t];
            if (k < mthr) { insert8u64(mk, k); mthr = mk[7]; }
        }
#pragma unroll
        for (int t = 0; t < 8; ++t)
            wiv[wid * 8 + t] = (int)(uint32_t)(mk[t] & 0xFFFFFFFFull);
    }
    __syncthreads();

    __shared__ float ed[64];
    {
        const float4* x4 = reinterpret_cast<const float4*>(X + (size_t)q * D_DIM);
        float4 xv[4];
#pragma unroll
        for (int jj = 0; jj < 4; ++jj) xv[jj] = x4[lane + jj * 32];
        for (int cc = 0; cc < 8; ++cc) {
            int idx = wiv[wid * 8 + cc];
            float d2 = 3.4e38f;
            if (idx >= 0 && idx < N) {
                const float4* t4 = reinterpret_cast<const float4*>(T + (size_t)idx * D_DIM);
                float dot = 0.f;
#pragma unroll
                for (int jj = 0; jj < 4; ++jj) {
                    float4 tv = t4[lane + jj * 32];
                    dot += xv[jj].x * tv.x + xv[jj].y * tv.y + xv[jj].z * tv.z + xv[jj].w * tv.w;
                }
#pragma unroll
                for (int o = 16; o; o >>= 1) dot += __shfl_xor_sync(0xffffffffu, dot, o);
                d2 = g_x2[q] + g_t2[idx] - 2.f * dot;
            }
            if (lane == 0) ed[wid * 8 + cc] = d2;
        }
    }
    __syncthreads();

    if (tid == 0) {
        float fd[5]; int fi[5];
#pragma unroll
        for (int t = 0; t < 5; ++t) { fd[t] = 3.4e38f; fi[t] = 0x7fffffff; }
        for (int t = 0; t < 64; ++t) {
            float vd = ed[t]; int vi = wiv[t];
#pragma unroll
            for (int jj = 0; jj < 5; ++jj) {
                bool lt = (vd < fd[jj]) || (vd == fd[jj] && vi < fi[jj]);
                if (lt) { float td = fd[jj]; int ti = fi[jj];
                          fd[jj] = vd; fi[jj] = vi; vd = td; vi = ti; }
            }
        }
        const int Q5 = Q * 5;
#pragma unroll
        for (int jj = 0; jj < 5; ++jj) {
            float dist = sqrtf(fmaxf(fd[jj], 0.f));
            int idx = fi[jj];
            int o0 = q * 5 + jj;
            int o1 = Q5 + q * 5 + jj;
            int o2 = 2 * Q5 + jj * Q + q;
            if (o0 < out_size) out[o0] = dist;
            if (o1 < out_size) out[o1] = (float)idx;
            if (o2 < out_size) out[o2] = (float)labels[idx];
        }
    }
}

// ---------------- launch -----------------------------------------------------
extern "C" void kernel_launch(void* const* d_in, const int* in_sizes, int n_in,
                              void* d_out, int out_size)
{
    const float* X      = (const float*)d_in[0];
    const float* T      = (const float*)d_in[1];
    const int*   labels = (const int*)d_in[2];
    const int Q = in_sizes[0] / D_DIM;
    const int N = in_sizes[2];

    convert_norm<<<(Q * 32 + 255) / 256, 256>>>(X, Q, Q, 0);
    convert_norm<<<(NPAD * 32 + 255) / 256, 256>>>(T, N, NPAD, 1);

    const int ntiles = (N + BN - 1) / BN;
    const int cstride = ntiles * 6;

    dim3 grid(ntiles, (Q + BM - 1) / BM);
    dist_gemm_mma<<<grid, 256>>>(N, Q, cstride);

    topk_rerank<<<Q, TKT>>>(X, T, labels, (float*)d_out, N, Q, out_size, cstride);
}